// round 1
// baseline (speedup 1.0000x reference)
#include <cuda_runtime.h>
#include <cuda_bf16.h>
#include <math.h>

#define NN 50000
#define NE 800000
#define INDIM 128
#define HID 64

// ---------------- device scratch (no allocations allowed) ----------------
__device__ int   g_deg[NN];
__device__ int   g_row_start[NN + 1];
__device__ int   g_cursor[NN];
__device__ int   g_csr[NE];
__device__ float g_invdeg[NN];
__device__ float g_z1[NN * INDIM];
__device__ float g_h1[NN * HID];
__device__ float g_z2[NN * HID];
__device__ float g_RS[NN * 128];      // per-node [R | S] with be1 folded into R
__device__ float g_Wcdt[64 * 128];    // bilinear weights, transposed [j][k]
__device__ float g_Wrs[64 * 128];     // [k][j'] combined R/S weights
__device__ float g_brs[128];

// ---------------- setup kernels ----------------
__global__ void k_zero() {
    int i = blockIdx.x * blockDim.x + threadIdx.x;
    if (i < NN) g_deg[i] = 0;
}

__global__ void k_count(const int* __restrict__ dst) {
    int e = blockIdx.x * blockDim.x + threadIdx.x;
    if (e < NE) atomicAdd(&g_deg[dst[e]], 1);
}

__global__ void k_scan() {
    __shared__ int wsum[32];
    __shared__ int carry;
    int tid = threadIdx.x;
    if (tid == 0) carry = 0;
    __syncthreads();
    for (int base = 0; base < NN; base += 1024) {
        int i = base + tid;
        int v = (i < NN) ? g_deg[i] : 0;
        int xv = v;
        #pragma unroll
        for (int o = 1; o < 32; o <<= 1) {
            int y = __shfl_up_sync(0xffffffffu, xv, o);
            if ((tid & 31) >= o) xv += y;
        }
        if ((tid & 31) == 31) wsum[tid >> 5] = xv;
        __syncthreads();
        if (tid < 32) {
            int s = wsum[tid];
            #pragma unroll
            for (int o = 1; o < 32; o <<= 1) {
                int y = __shfl_up_sync(0xffffffffu, s, o);
                if (tid >= o) s += y;
            }
            wsum[tid] = s;
        }
        __syncthreads();
        int add = (tid >= 32) ? wsum[(tid >> 5) - 1] : 0;
        int incl = xv + add + carry;
        if (i < NN) {
            g_row_start[i] = incl - v;
            g_cursor[i]    = incl - v;
            g_invdeg[i]    = 1.0f / fmaxf((float)v, 1.0f);
        }
        __syncthreads();
        if (tid == 1023) carry = incl;
        __syncthreads();
    }
    if (tid == 0) g_row_start[NN] = carry;
}

__global__ void k_bucket(const int* __restrict__ src, const int* __restrict__ dst) {
    int e = blockIdx.x * blockDim.x + threadIdx.x;
    if (e < NE) {
        int d = dst[e];
        int p = atomicAdd(&g_cursor[d], 1);
        g_csr[p] = src[e];
    }
}

__global__ void k_prep(const float* __restrict__ We1, const float* __restrict__ be1) {
    int i = blockIdx.x * blockDim.x + threadIdx.x;
    if (i < 64 * 128) {
        int j = i >> 7, k = i & 127;
        // bilinear block rows of We1: rows 128..255; row = 128+k for both halves
        g_Wcdt[i] = We1[(128 + k) * 64 + j];
        int kk = i >> 7, jj = i & 127; // Wrs[k][j']
        g_Wrs[i] = (jj < 64) ? We1[kk * 64 + jj]
                             : We1[(64 + kk) * 64 + (jj - 64)];
    }
    if (i < 128) g_brs[i] = (i < 64) ? be1[i] : 0.0f;
}

// ---------------- mean aggregation (gather via CSR) ----------------
template <int D>
__global__ void k_agg(const float* __restrict__ h, float* __restrict__ z) {
    int n = blockIdx.x, k = threadIdx.x;
    int beg = g_row_start[n], end = g_row_start[n + 1];
    float acc = 0.0f;
    int e = beg;
    for (; e + 1 < end; e += 2) {
        int s0 = __ldg(&g_csr[e]);
        int s1 = __ldg(&g_csr[e + 1]);
        acc += h[s0 * D + k];
        acc += h[s1 * D + k];
    }
    if (e < end) {
        int s = __ldg(&g_csr[e]);
        acc += h[s * D + k];
    }
    z[n * D + k] = h[n * D + k] + acc * g_invdeg[n];
}

// ---------------- small dense GEMM: out = act(Z @ W + bias) ----------------
template <int K, int NC, bool RELU>
__global__ void __launch_bounds__(NC) k_gemm(const float* __restrict__ Z,
                                             const float* __restrict__ W,
                                             const float* __restrict__ bias,
                                             float* __restrict__ out) {
    constexpr int KP = K + 4;
    constexpr int RT = 8;
    __shared__ float Ws[NC * KP];
    __shared__ float Zs[RT * KP];
    int j = threadIdx.x;
    for (int idx = j; idx < K * NC; idx += NC) {
        int k = idx / NC, c = idx - k * NC;
        Ws[c * KP + k] = W[idx];
    }
    float bj = bias[j];
    int row0 = blockIdx.x * RT;
    for (int idx = j; idx < RT * K; idx += NC) {
        int r = idx / K, k = idx - r * K;
        Zs[r * KP + k] = Z[(row0 + r) * K + k];
    }
    __syncthreads();
    float acc[RT];
    #pragma unroll
    for (int r = 0; r < RT; r++) acc[r] = bj;
    const float4* w4 = reinterpret_cast<const float4*>(&Ws[j * KP]);
    #pragma unroll 8
    for (int k4 = 0; k4 < K / 4; k4++) {
        float4 w = w4[k4];
        #pragma unroll
        for (int r = 0; r < RT; r++) {
            float4 z = *reinterpret_cast<const float4*>(&Zs[r * KP + k4 * 4]);
            acc[r] += z.x * w.x;
            acc[r] += z.y * w.y;
            acc[r] += z.z * w.z;
            acc[r] += z.w * w.w;
        }
    }
    #pragma unroll
    for (int r = 0; r < RT; r++) {
        float v = acc[r];
        if (RELU) v = fmaxf(v, 0.0f);
        out[(row0 + r) * NC + j] = v;
    }
}

// ---------------- fused edge MLP ----------------
// hidden_j = rs_j + sum_k a_k * Bt[j][k],  a = [hs*hd | abs(hs-hd)] (128)
// logit = sum_j relu(hidden_j) * We2[j] + be2 ; prob = sigmoid(logit)
#define TE 64
#define NTILES (NE / TE)

__global__ void __launch_bounds__(256, 2) k_edge(const float* __restrict__ H,
                                                 const int* __restrict__ src,
                                                 const int* __restrict__ dst,
                                                 const float* __restrict__ We2,
                                                 const float* __restrict__ be2,
                                                 float* __restrict__ logits,
                                                 float* __restrict__ probs) {
    extern __shared__ float sh[];
    float* sB  = sh;                   // [64][132]
    float* sA  = sB + 64 * 132;        // [TE][132]  (p | q)
    float* sRS = sA + TE * 132;        // [TE][68]
    float* sW2 = sRS + TE * 68;        // [64]
    int*   ssrc = (int*)(sW2 + 64);    // [TE]
    int*   sdst = ssrc + TE;           // [TE]

    int tid = threadIdx.x;
    for (int idx = tid; idx < 64 * 128; idx += 256) {
        int j = idx >> 7, k = idx & 127;
        sB[j * 132 + k] = g_Wcdt[idx];
    }
    if (tid < 64) sW2[tid] = We2[tid];
    float be2v = be2[0];

    int cg = tid & 15, eg = tid >> 4;       // col-group, edge-group
    int se = tid >> 2, k0 = (tid & 3) << 4; // staging assignment

    for (int tile = blockIdx.x; tile < NTILES; tile += gridDim.x) {
        __syncthreads();  // protect sA/sRS from previous tile's readers
        int e0 = tile * TE;
        if (tid < TE) {
            ssrc[tid] = src[e0 + tid];
            sdst[tid] = dst[e0 + tid];
        }
        __syncthreads();

        // ---- stage A (p,q) and rs accumInit ----
        int s = ssrc[se], d = sdst[se];
        const float4* hs4 = reinterpret_cast<const float4*>(H + s * 64 + k0);
        const float4* hd4 = reinterpret_cast<const float4*>(H + d * 64 + k0);
        #pragma unroll
        for (int q = 0; q < 4; q++) {
            float4 a = hs4[q], b = hd4[q];
            int k = k0 + q * 4;
            float4 p  = {a.x * b.x, a.y * b.y, a.z * b.z, a.w * b.w};
            float4 qd = {fabsf(a.x - b.x), fabsf(a.y - b.y),
                         fabsf(a.z - b.z), fabsf(a.w - b.w)};
            *reinterpret_cast<float4*>(&sA[se * 132 + k])      = p;
            *reinterpret_cast<float4*>(&sA[se * 132 + 64 + k]) = qd;
        }
        const float4* r4 = reinterpret_cast<const float4*>(g_RS + s * 128 + k0);
        const float4* t4 = reinterpret_cast<const float4*>(g_RS + d * 128 + 64 + k0);
        #pragma unroll
        for (int q = 0; q < 4; q++) {
            float4 r = r4[q], t = t4[q];
            float4 u = {r.x + t.x, r.y + t.y, r.z + t.z, r.w + t.w};
            *reinterpret_cast<float4*>(&sRS[se * 68 + k0 + q * 4]) = u;
        }
        __syncthreads();

        // ---- register-blocked bilinear GEMM: 4 edges x 4 cols per thread ----
        int eb = eg * 4, jb = cg * 4;
        float acc[4][4];
        #pragma unroll
        for (int ee = 0; ee < 4; ee++)
            #pragma unroll
            for (int jj = 0; jj < 4; jj++)
                acc[ee][jj] = sRS[(eb + ee) * 68 + jb + jj];

        #pragma unroll 8
        for (int k4 = 0; k4 < 32; k4++) {
            float4 bf[4], af[4];
            #pragma unroll
            for (int jj = 0; jj < 4; jj++)
                bf[jj] = *reinterpret_cast<const float4*>(&sB[(jb + jj) * 132 + k4 * 4]);
            #pragma unroll
            for (int ee = 0; ee < 4; ee++)
                af[ee] = *reinterpret_cast<const float4*>(&sA[(eb + ee) * 132 + k4 * 4]);
            #pragma unroll
            for (int ee = 0; ee < 4; ee++)
                #pragma unroll
                for (int jj = 0; jj < 4; jj++) {
                    acc[ee][jj] += af[ee].x * bf[jj].x;
                    acc[ee][jj] += af[ee].y * bf[jj].y;
                    acc[ee][jj] += af[ee].z * bf[jj].z;
                    acc[ee][jj] += af[ee].w * bf[jj].w;
                }
        }

        // ---- fused epilogue: relu -> dot(We2) -> reduce over 16 col-groups ----
        float part[4];
        #pragma unroll
        for (int ee = 0; ee < 4; ee++) {
            float psum = 0.0f;
            #pragma unroll
            for (int jj = 0; jj < 4; jj++)
                psum += fmaxf(acc[ee][jj], 0.0f) * sW2[jb + jj];
            part[ee] = psum;
        }
        #pragma unroll
        for (int o = 8; o; o >>= 1)
            #pragma unroll
            for (int ee = 0; ee < 4; ee++)
                part[ee] += __shfl_xor_sync(0xffffffffu, part[ee], o);
        if (cg == 0) {
            #pragma unroll
            for (int ee = 0; ee < 4; ee++) {
                float lg = part[ee] + be2v;
                int ei = e0 + eb + ee;
                logits[ei] = lg;
                probs[ei]  = 1.0f / (1.0f + expf(-lg));
            }
        }
    }
}

// ---------------- launcher ----------------
extern "C" void kernel_launch(void* const* d_in, const int* in_sizes, int n_in,
                              void* d_out, int out_size) {
    const float* x   = (const float*)d_in[0];
    const float* W1  = (const float*)d_in[1];
    const float* b1  = (const float*)d_in[2];
    const float* W2  = (const float*)d_in[3];
    const float* b2  = (const float*)d_in[4];
    const float* We1 = (const float*)d_in[5];
    const float* be1 = (const float*)d_in[6];
    const float* We2 = (const float*)d_in[7];
    const float* be2 = (const float*)d_in[8];
    const int*   ei  = (const int*)d_in[9];
    const int* src = ei;
    const int* dst = ei + NE;

    float* out    = (float*)d_out;
    float* H      = out;                 // [NN, 64]
    float* logits = out + NN * HID;      // [NE]
    float* probs  = logits + NE;         // [NE]

    void *z1p, *h1p, *z2p, *RSp, *Wrsp, *brsp;
    cudaGetSymbolAddress(&z1p, g_z1);
    cudaGetSymbolAddress(&h1p, g_h1);
    cudaGetSymbolAddress(&z2p, g_z2);
    cudaGetSymbolAddress(&RSp, g_RS);
    cudaGetSymbolAddress(&Wrsp, g_Wrs);
    cudaGetSymbolAddress(&brsp, g_brs);

    // CSR build
    k_zero<<<(NN + 255) / 256, 256>>>();
    k_count<<<(NE + 255) / 256, 256>>>(dst);
    k_scan<<<1, 1024>>>();
    k_bucket<<<(NE + 255) / 256, 256>>>(src, dst);
    k_prep<<<32, 256>>>(We1, be1);

    // encoder layer 1
    k_agg<INDIM><<<NN, INDIM>>>(x, (float*)z1p);
    k_gemm<INDIM, HID, true><<<NN / 8, HID>>>((const float*)z1p, W1, b1, (float*)h1p);
    // encoder layer 2 -> H into d_out
    k_agg<HID><<<NN, HID>>>((const float*)h1p, (float*)z2p);
    k_gemm<HID, HID, true><<<NN / 8, HID>>>((const float*)z2p, W2, b2, H);
    // per-node R|S precompute (be1 folded)
    k_gemm<HID, 128, false><<<NN / 8, 128>>>(H, (const float*)Wrsp,
                                             (const float*)brsp, (float*)RSp);

    // fused edge MLP
    int shmem = (64 * 132 + TE * 132 + TE * 68 + 64) * (int)sizeof(float)
                + 2 * TE * (int)sizeof(int);
    cudaFuncSetAttribute(k_edge, cudaFuncAttributeMaxDynamicSharedMemorySize, shmem);
    k_edge<<<296, 256, shmem>>>(H, src, dst, We2, be2, logits, probs);
}

// round 2
// speedup vs baseline: 1.4602x; 1.4602x over previous
#include <cuda_runtime.h>
#include <math.h>

#define NN 50000
#define NE 800000
#define INDIM 128
#define HID 64

// ---------------- device scratch (no allocations allowed) ----------------
__device__ int   g_deg[NN];
__device__ int   g_row_start[NN + 1];
__device__ int   g_cursor[NN];
__device__ int   g_csr[NE];
__device__ float g_invdeg[NN];
__device__ float g_y[NN * HID];       // y = h @ W (pre-aggregation)
__device__ float g_h1[NN * HID];
__device__ float g_y2[NN * HID];
__device__ float g_RS[NN * 128];      // per-node [R | S], be1 folded into R
__device__ float g_Wrs[64 * 128];     // combined R/S weights [k][j']
__device__ float g_brs[128];
__device__ float g_zeros[128];        // static-zeroed

// ---------------- setup kernels ----------------
__global__ void k_zero() {
    int i = blockIdx.x * blockDim.x + threadIdx.x;
    if (i < NN) g_deg[i] = 0;
}

__global__ void k_count(const int* __restrict__ dst) {
    int e = blockIdx.x * blockDim.x + threadIdx.x;
    if (e < NE) atomicAdd(&g_deg[dst[e]], 1);
}

__global__ void k_scan() {
    __shared__ int wsum[32];
    __shared__ int carry;
    int tid = threadIdx.x;
    if (tid == 0) carry = 0;
    __syncthreads();
    for (int base = 0; base < NN; base += 1024) {
        int i = base + tid;
        int v = (i < NN) ? g_deg[i] : 0;
        int xv = v;
        #pragma unroll
        for (int o = 1; o < 32; o <<= 1) {
            int y = __shfl_up_sync(0xffffffffu, xv, o);
            if ((tid & 31) >= o) xv += y;
        }
        if ((tid & 31) == 31) wsum[tid >> 5] = xv;
        __syncthreads();
        if (tid < 32) {
            int s = wsum[tid];
            #pragma unroll
            for (int o = 1; o < 32; o <<= 1) {
                int y = __shfl_up_sync(0xffffffffu, s, o);
                if (tid >= o) s += y;
            }
            wsum[tid] = s;
        }
        __syncthreads();
        int add = (tid >= 32) ? wsum[(tid >> 5) - 1] : 0;
        int incl = xv + add + carry;
        if (i < NN) {
            g_row_start[i] = incl - v;
            g_cursor[i]    = incl - v;
            g_invdeg[i]    = 1.0f / fmaxf((float)v, 1.0f);
        }
        __syncthreads();
        if (tid == 1023) carry = incl;
        __syncthreads();
    }
    if (tid == 0) g_row_start[NN] = carry;
}

__global__ void k_bucket(const int* __restrict__ src, const int* __restrict__ dst) {
    int e = blockIdx.x * blockDim.x + threadIdx.x;
    if (e < NE) {
        int d = dst[e];
        int p = atomicAdd(&g_cursor[d], 1);
        g_csr[p] = src[e];
    }
}

__global__ void k_prep(const float* __restrict__ We1, const float* __restrict__ be1) {
    int i = blockIdx.x * blockDim.x + threadIdx.x;
    if (i < 64 * 128) {
        int kk = i >> 7, jj = i & 127;  // Wrs[k][j']
        g_Wrs[i] = (jj < 64) ? We1[kk * 64 + jj]
                             : We1[(64 + kk) * 64 + (jj - 64)];
    }
    if (i < 128) g_brs[i] = (i < 64) ? be1[i] : 0.0f;
}

// ------- mean aggregation on 64-dim (fused bias + relu): out = relu(y + agg(y)/deg + b)
__global__ void __launch_bounds__(256) k_aggr(const float* __restrict__ y,
                                              const float* __restrict__ bias,
                                              float* __restrict__ out) {
    int node = blockIdx.x * 4 + (threadIdx.x >> 6);
    int k = threadIdx.x & 63;
    int beg = g_row_start[node], end = g_row_start[node + 1];
    float acc = 0.0f;
    int e = beg;
    for (; e + 1 < end; e += 2) {
        int s0 = __ldg(&g_csr[e]);
        int s1 = __ldg(&g_csr[e + 1]);
        acc += y[s0 * 64 + k];
        acc += y[s1 * 64 + k];
    }
    if (e < end) acc += y[__ldg(&g_csr[e]) * 64 + k];
    float v = y[node * 64 + k] + acc * g_invdeg[node] + bias[k];
    out[node * 64 + k] = fmaxf(v, 0.0f);
}

// ---------------- small dense GEMM: out = Z @ W + bias ----------------
template <int K, int NC>
__global__ void __launch_bounds__(NC) k_gemm(const float* __restrict__ Z,
                                             const float* __restrict__ W,
                                             const float* __restrict__ bias,
                                             float* __restrict__ out) {
    constexpr int KP = K + 4;
    constexpr int RT = 8;
    __shared__ float Ws[NC * KP];
    __shared__ float Zs[RT * KP];
    int j = threadIdx.x;
    for (int idx = j; idx < K * NC; idx += NC) {
        int k = idx / NC, c = idx - k * NC;
        Ws[c * KP + k] = W[idx];
    }
    float bj = bias[j];
    int row0 = blockIdx.x * RT;
    for (int idx = j; idx < RT * K; idx += NC) {
        int r = idx / K, k = idx - r * K;
        Zs[r * KP + k] = Z[(row0 + r) * K + k];
    }
    __syncthreads();
    float acc[RT];
    #pragma unroll
    for (int r = 0; r < RT; r++) acc[r] = bj;
    const float4* w4 = reinterpret_cast<const float4*>(&Ws[j * KP]);
    #pragma unroll 8
    for (int k4 = 0; k4 < K / 4; k4++) {
        float4 w = w4[k4];
        #pragma unroll
        for (int r = 0; r < RT; r++) {
            float4 z = *reinterpret_cast<const float4*>(&Zs[r * KP + k4 * 4]);
            acc[r] += z.x * w.x;
            acc[r] += z.y * w.y;
            acc[r] += z.z * w.z;
            acc[r] += z.w * w.w;
        }
    }
    #pragma unroll
    for (int r = 0; r < RT; r++)
        out[(row0 + r) * NC + j] = acc[r];
}

// ---------------- fused edge MLP with packed fp32 (fma.rn.f32x2) ----------------
// hidden_j = rs_j + sum_k a_k * B[k][j],  a = [hs*hd | abs(hs-hd)] (128)
// logit = sum_j relu(hidden_j) * We2[j] + be2 ; prob = sigmoid(logit)
// Acc pairs over edges: A pairs contiguous in sAT[k][e]; B pre-duplicated.
#define FMA2(c, a, b) asm("fma.rn.f32x2 %0, %1, %2, %3;" \
                          : "=l"(c) : "l"(a), "l"(b), "l"(c))

__device__ __forceinline__ unsigned long long pk(float lo, float hi) {
    unsigned long long r = (unsigned long long)__float_as_uint(lo);
    return r | ((unsigned long long)__float_as_uint(hi) << 32);
}

#define SB2S 136
#define SATS 260
#define NTILES 3125   // 800000 / 256

__global__ void __launch_bounds__(256, 1) k_edge(
    const float* __restrict__ H, const int* __restrict__ src,
    const int* __restrict__ dst, const float* __restrict__ We1,
    const float* __restrict__ We2, const float* __restrict__ be2,
    float* __restrict__ logits, float* __restrict__ probs) {
    extern __shared__ float sh[];
    float* sB2 = sh;                    // [128][136] duplicated B
    float* sAT = sB2 + 128 * SB2S;      // [128 k][260] (256 e + pad)
    float* sW2 = sAT + 128 * SATS;      // [64]
    int*   ssrc = (int*)(sW2 + 64);     // [256]
    int*   sdst = ssrc + 256;           // [256]
    int tid = threadIdx.x;

    // stage duplicated B once per block: B[k][j] = We1[(128+k)*64 + j]
    for (int idx = tid; idx < 128 * 64; idx += 256) {
        int k = idx >> 6, j = idx & 63;
        float b = We1[(128 + k) * 64 + j];
        sB2[k * SB2S + 2 * j]     = b;
        sB2[k * SB2S + 2 * j + 1] = b;
    }
    if (tid < 64) sW2[tid] = We2[tid];
    float be2v = be2[0];

    int eg = tid >> 4, jg = tid & 15, jb = jg * 4;

    for (int tile = blockIdx.x; tile < NTILES; tile += gridDim.x) {
        __syncthreads();  // protect sAT/ssrc from previous tile's readers
        int e0 = tile * 256;
        ssrc[tid] = src[e0 + tid];
        sdst[tid] = dst[e0 + tid];
        __syncthreads();

        // ---- stage sAT[k][e]: p at k<64, q at k>=64; thread owns edge tid ----
        {
            int s = ssrc[tid], d = sdst[tid];
            const float4* hs4 = reinterpret_cast<const float4*>(H + (size_t)s * 64);
            const float4* hd4 = reinterpret_cast<const float4*>(H + (size_t)d * 64);
            float* pa = sAT + tid;
            #pragma unroll
            for (int c = 0; c < 16; c++) {
                float4 a = hs4[c], b = hd4[c];
                pa[(4 * c + 0) * SATS] = a.x * b.x;
                pa[(4 * c + 1) * SATS] = a.y * b.y;
                pa[(4 * c + 2) * SATS] = a.z * b.z;
                pa[(4 * c + 3) * SATS] = a.w * b.w;
                pa[(64 + 4 * c + 0) * SATS] = fabsf(a.x - b.x);
                pa[(64 + 4 * c + 1) * SATS] = fabsf(a.y - b.y);
                pa[(64 + 4 * c + 2) * SATS] = fabsf(a.z - b.z);
                pa[(64 + 4 * c + 3) * SATS] = fabsf(a.w - b.w);
            }
        }
        __syncthreads();

        // ---- acc init from RS (gmem, L2-resident) ----
        unsigned long long acc[8][4];
        #pragma unroll
        for (int ep = 0; ep < 8; ep++) {
            int ea = eg * 16 + 2 * ep;
            int s0 = ssrc[ea],     d0 = sdst[ea];
            int s1 = ssrc[ea + 1], d1 = sdst[ea + 1];
            float4 r0 = *reinterpret_cast<const float4*>(g_RS + (size_t)s0 * 128 + jb);
            float4 t0 = *reinterpret_cast<const float4*>(g_RS + (size_t)d0 * 128 + 64 + jb);
            float4 r1 = *reinterpret_cast<const float4*>(g_RS + (size_t)s1 * 128 + jb);
            float4 t1 = *reinterpret_cast<const float4*>(g_RS + (size_t)d1 * 128 + 64 + jb);
            acc[ep][0] = pk(r0.x + t0.x, r1.x + t1.x);
            acc[ep][1] = pk(r0.y + t0.y, r1.y + t1.y);
            acc[ep][2] = pk(r0.z + t0.z, r1.z + t1.z);
            acc[ep][3] = pk(r0.w + t0.w, r1.w + t1.w);
        }

        // ---- mainloop: 32 FMA2 + 6 LDS.128 per thread per k ----
        const float* satBase = sAT + eg * 16;
        const float* sb2Base = sB2 + jg * 8;
        #pragma unroll 4
        for (int k = 0; k < 128; k++) {
            const ulonglong2* ap =
                reinterpret_cast<const ulonglong2*>(satBase + k * SATS);
            const ulonglong2* bp =
                reinterpret_cast<const ulonglong2*>(sb2Base + k * SB2S);
            ulonglong2 B01 = bp[0], B23 = bp[1];
            ulonglong2 A0 = ap[0], A1 = ap[1], A2 = ap[2], A3 = ap[3];
            unsigned long long av[8] = {A0.x, A0.y, A1.x, A1.y,
                                        A2.x, A2.y, A3.x, A3.y};
            unsigned long long bv[4] = {B01.x, B01.y, B23.x, B23.y};
            #pragma unroll
            for (int ep = 0; ep < 8; ep++)
                #pragma unroll
                for (int j = 0; j < 4; j++)
                    FMA2(acc[ep][j], av[ep], bv[j]);
        }

        // ---- epilogue: relu -> dot(We2) -> reduce over 16 jg lanes ----
        float part[16];
        #pragma unroll
        for (int ep = 0; ep < 8; ep++) {
            float pe = 0.0f, po = 0.0f;
            #pragma unroll
            for (int j = 0; j < 4; j++) {
                float lo = __uint_as_float((unsigned)acc[ep][j]);
                float hi = __uint_as_float((unsigned)(acc[ep][j] >> 32));
                float w = sW2[jb + j];
                pe += fmaxf(lo, 0.0f) * w;
                po += fmaxf(hi, 0.0f) * w;
            }
            part[2 * ep]     = pe;
            part[2 * ep + 1] = po;
        }
        #pragma unroll
        for (int o = 1; o < 16; o <<= 1)
            #pragma unroll
            for (int i = 0; i < 16; i++)
                part[i] += __shfl_xor_sync(0xffffffffu, part[i], o);
        if (jg == 0) {
            #pragma unroll
            for (int i = 0; i < 16; i++) {
                int e = e0 + eg * 16 + i;
                float lg = part[i] + be2v;
                logits[e] = lg;
                probs[e]  = 1.0f / (1.0f + expf(-lg));
            }
        }
    }
}

// ---------------- launcher ----------------
extern "C" void kernel_launch(void* const* d_in, const int* in_sizes, int n_in,
                              void* d_out, int out_size) {
    const float* x   = (const float*)d_in[0];
    const float* W1  = (const float*)d_in[1];
    const float* b1  = (const float*)d_in[2];
    const float* W2  = (const float*)d_in[3];
    const float* b2  = (const float*)d_in[4];
    const float* We1 = (const float*)d_in[5];
    const float* be1 = (const float*)d_in[6];
    const float* We2 = (const float*)d_in[7];
    const float* be2 = (const float*)d_in[8];
    const int*   ei  = (const int*)d_in[9];
    const int* src = ei;
    const int* dst = ei + NE;

    float* out    = (float*)d_out;
    float* H      = out;                 // [NN, 64]
    float* logits = out + NN * HID;      // [NE]
    float* probs  = logits + NE;         // [NE]

    void *yp, *h1p, *y2p, *RSp, *Wrsp, *brsp, *zp;
    cudaGetSymbolAddress(&yp, g_y);
    cudaGetSymbolAddress(&h1p, g_h1);
    cudaGetSymbolAddress(&y2p, g_y2);
    cudaGetSymbolAddress(&RSp, g_RS);
    cudaGetSymbolAddress(&Wrsp, g_Wrs);
    cudaGetSymbolAddress(&brsp, g_brs);
    cudaGetSymbolAddress(&zp, g_zeros);

    // CSR build
    k_zero<<<(NN + 255) / 256, 256>>>();
    k_count<<<(NE + 255) / 256, 256>>>(dst);
    k_scan<<<1, 1024>>>();
    k_bucket<<<(NE + 255) / 256, 256>>>(src, dst);
    k_prep<<<32, 256>>>(We1, be1);

    // encoder layer 1 (GEMM first, then 64-dim aggregation; linearity commute)
    k_gemm<INDIM, HID><<<NN / 8, HID>>>(x, W1, (const float*)zp, (float*)yp);
    k_aggr<<<NN / 4, 256>>>((const float*)yp, b1, (float*)h1p);
    // encoder layer 2 -> H into d_out
    k_gemm<HID, HID><<<NN / 8, HID>>>((const float*)h1p, W2, (const float*)zp,
                                      (float*)y2p);
    k_aggr<<<NN / 4, 256>>>((const float*)y2p, b2, H);
    // per-node R|S precompute (be1 folded)
    k_gemm<HID, 128><<<NN / 8, 128>>>(H, (const float*)Wrsp,
                                      (const float*)brsp, (float*)RSp);

    // fused edge MLP (persistent, f32x2)
    int shmem = (128 * SB2S + 128 * SATS + 64) * (int)sizeof(float)
                + 512 * (int)sizeof(int);
    cudaFuncSetAttribute(k_edge, cudaFuncAttributeMaxDynamicSharedMemorySize,
                         shmem);
    k_edge<<<148, 256, shmem>>>(H, src, dst, We1, We2, be2, logits, probs);
}

// round 4
// speedup vs baseline: 2.4766x; 1.6961x over previous
#include <cuda_runtime.h>
#include <cuda_fp16.h>
#include <cstdint>
#include <math.h>

#define NN 50000
#define NE 800000
#define INDIM 128
#define HID 64

// ======================= device scratch =======================
__device__ int   g_deg[NN];
__device__ int   g_row_start[NN + 1];
__device__ int   g_cursor[NN];
__device__ int   g_csr[NE];
__device__ float g_invdeg[NN];
__device__ float g_y[NN * HID];
__device__ float g_h1[NN * HID];
__device__ float g_y2[NN * HID];
__device__ float g_zeros[128];

// ======================= CSR build =======================
__global__ void k_zero() {
    int i = blockIdx.x * blockDim.x + threadIdx.x;
    if (i < NN) g_deg[i] = 0;
}

__global__ void k_count(const int* __restrict__ dst) {
    int e = blockIdx.x * blockDim.x + threadIdx.x;
    if (e < NE) atomicAdd(&g_deg[dst[e]], 1);
}

__global__ void k_scan() {
    __shared__ int wsum[32];
    __shared__ int carry;
    int tid = threadIdx.x;
    if (tid == 0) carry = 0;
    __syncthreads();
    for (int base = 0; base < NN; base += 1024) {
        int i = base + tid;
        int v = (i < NN) ? g_deg[i] : 0;
        int xv = v;
        #pragma unroll
        for (int o = 1; o < 32; o <<= 1) {
            int y = __shfl_up_sync(0xffffffffu, xv, o);
            if ((tid & 31) >= o) xv += y;
        }
        if ((tid & 31) == 31) wsum[tid >> 5] = xv;
        __syncthreads();
        if (tid < 32) {
            int s = wsum[tid];
            #pragma unroll
            for (int o = 1; o < 32; o <<= 1) {
                int y = __shfl_up_sync(0xffffffffu, s, o);
                if (tid >= o) s += y;
            }
            wsum[tid] = s;
        }
        __syncthreads();
        int add = (tid >= 32) ? wsum[(tid >> 5) - 1] : 0;
        int incl = xv + add + carry;
        if (i < NN) {
            g_row_start[i] = incl - v;
            g_cursor[i]    = incl - v;
            g_invdeg[i]    = 1.0f / fmaxf((float)v, 1.0f);
        }
        __syncthreads();
        if (tid == 1023) carry = incl;
        __syncthreads();
    }
    if (tid == 0) g_row_start[NN] = carry;
}

__global__ void k_bucket(const int* __restrict__ src, const int* __restrict__ dst) {
    int e = blockIdx.x * blockDim.x + threadIdx.x;
    if (e < NE) {
        int d = dst[e];
        int p = atomicAdd(&g_cursor[d], 1);
        g_csr[p] = src[e];
    }
}

// ======= mean aggregation (fused bias + relu): out = relu(y + agg(y)/deg + b)
__global__ void __launch_bounds__(256) k_aggr(const float* __restrict__ y,
                                              const float* __restrict__ bias,
                                              float* __restrict__ out) {
    int node = blockIdx.x * 4 + (threadIdx.x >> 6);
    int k = threadIdx.x & 63;
    int beg = g_row_start[node], end = g_row_start[node + 1];
    float acc = 0.0f;
    int e = beg;
    for (; e + 1 < end; e += 2) {
        int s0 = __ldg(&g_csr[e]);
        int s1 = __ldg(&g_csr[e + 1]);
        acc += y[s0 * 64 + k];
        acc += y[s1 * 64 + k];
    }
    if (e < end) acc += y[__ldg(&g_csr[e]) * 64 + k];
    float v = y[node * 64 + k] + acc * g_invdeg[node] + bias[k];
    out[node * 64 + k] = fmaxf(v, 0.0f);
}

// ======================= small dense GEMM: out = Z @ W + bias =======================
template <int K, int NC>
__global__ void __launch_bounds__(NC) k_gemm(const float* __restrict__ Z,
                                             const float* __restrict__ W,
                                             const float* __restrict__ bias,
                                             float* __restrict__ out) {
    constexpr int KP = K + 4;
    constexpr int RT = 8;
    __shared__ float Ws[NC * KP];
    __shared__ float Zs[RT * KP];
    int j = threadIdx.x;
    for (int idx = j; idx < K * NC; idx += NC) {
        int k = idx / NC, c = idx - k * NC;
        Ws[c * KP + k] = W[idx];
    }
    float bj = bias[j];
    int row0 = blockIdx.x * RT;
    for (int idx = j; idx < RT * K; idx += NC) {
        int r = idx / K, k = idx - r * K;
        Zs[r * KP + k] = Z[(row0 + r) * K + k];
    }
    __syncthreads();
    float acc[RT];
    #pragma unroll
    for (int r = 0; r < RT; r++) acc[r] = bj;
    const float4* w4 = reinterpret_cast<const float4*>(&Ws[j * KP]);
    #pragma unroll 8
    for (int k4 = 0; k4 < K / 4; k4++) {
        float4 w = w4[k4];
        #pragma unroll
        for (int r = 0; r < RT; r++) {
            float4 z = *reinterpret_cast<const float4*>(&Zs[r * KP + k4 * 4]);
            acc[r] += z.x * w.x;
            acc[r] += z.y * w.y;
            acc[r] += z.z * w.z;
            acc[r] += z.w * w.w;
        }
    }
    #pragma unroll
    for (int r = 0; r < RT; r++)
        out[(row0 + r) * NC + j] = acc[r];
}

// ======================= fused edge MLP on mma.sync (HMMA.16816) =======================
// Per 128-edge tile: A'[128 x 256] = [hs|hd|p|q] split fp16 hi/lo in smem.
// B = fp16(We1) [256 x 64] held in REGISTERS (per-warp fragments), loaded once.
// D (fp32) = Ah*Bh + Al*Bh = A*Bh exactly; only B quantization error (~1.2e-4).
// Epilogue in registers: relu(D+be1) . We2, quad-shuffle reduce, smem combine.
#define ET 128
#define ETILES (NE / ET)         // 6250
#define ROWB 528                 // 264 halfs per A row (8-half pad)
#define OFF_AH 1024
#define OFF_AL (OFF_AH + 128 * ROWB)          // 68608
#define SMEM_EDGE (OFF_AL + 128 * ROWB)       // 136192 bytes

__device__ __forceinline__ uint32_t smem_u32(const void* p) {
    uint32_t a;
    asm("{ .reg .u64 t; cvta.to.shared.u64 t, %1; cvt.u32.u64 %0, t; }"
        : "=r"(a) : "l"(p));
    return a;
}

#define LDSM4(r, addr)                                                         \
    asm volatile("ldmatrix.sync.aligned.m8n8.x4.shared.b16 {%0,%1,%2,%3}, [%4];" \
                 : "=r"((r)[0]), "=r"((r)[1]), "=r"((r)[2]), "=r"((r)[3])      \
                 : "r"(addr))

#define MMA16816(d, a, b)                                                      \
    asm volatile("mma.sync.aligned.m16n8k16.row.col.f32.f16.f16.f32 "          \
                 "{%0,%1,%2,%3},{%4,%5,%6,%7},{%8,%9},{%0,%1,%2,%3};"          \
                 : "+f"((d)[0]), "+f"((d)[1]), "+f"((d)[2]), "+f"((d)[3])      \
                 : "r"((a)[0]), "r"((a)[1]), "r"((a)[2]), "r"((a)[3]),         \
                   "r"((b)[0]), "r"((b)[1]))

__device__ __forceinline__ void write8(char* ah, char* al, int koff2,
                                       const float* v) {
    uint32_t hi[4], lo[4];
    #pragma unroll
    for (int i = 0; i < 4; i++) {
        __half2 h = __floats2half2_rn(v[2 * i], v[2 * i + 1]);
        float2 hf = __half22float2(h);
        __half2 l = __floats2half2_rn(v[2 * i] - hf.x, v[2 * i + 1] - hf.y);
        hi[i] = *reinterpret_cast<uint32_t*>(&h);
        lo[i] = *reinterpret_cast<uint32_t*>(&l);
    }
    *reinterpret_cast<uint4*>(ah + koff2) = make_uint4(hi[0], hi[1], hi[2], hi[3]);
    *reinterpret_cast<uint4*>(al + koff2) = make_uint4(lo[0], lo[1], lo[2], lo[3]);
}

__global__ void __launch_bounds__(256, 1) k_edge(
    const float* __restrict__ H, const int* __restrict__ src,
    const int* __restrict__ dst, const float* __restrict__ We1,
    const float* __restrict__ be1, const float* __restrict__ We2,
    const float* __restrict__ be2,
    float* __restrict__ logits, float* __restrict__ probs) {
    extern __shared__ char sm[];
    float* sred = reinterpret_cast<float*>(sm);       // 256 floats
    char* AhB = sm + OFF_AH;
    char* AlB = sm + OFF_AL;

    int tid = threadIdx.x, lane = tid & 31, wid = tid >> 5;
    int mw = wid & 3, nw = wid >> 2;

    // ---- load B fragments into registers (once per block) ----
    uint32_t bF[16][4][2];
    #pragma unroll
    for (int s = 0; s < 16; s++)
        #pragma unroll
        for (int j = 0; j < 4; j++)
            #pragma unroll
            for (int r = 0; r < 2; r++) {
                int k = s * 16 + 2 * (lane & 3) + r * 8;
                int n = nw * 32 + j * 8 + (lane >> 2);
                __half2 h = __floats2half2_rn(__ldg(&We1[k * 64 + n]),
                                              __ldg(&We1[(k + 1) * 64 + n]));
                bF[s][j][r] = *reinterpret_cast<uint32_t*>(&h);
            }
    // epilogue constants: cols nc = nw*32 + 8j + 2*(lane&3) + c
    float bb[4][2], ww[4][2];
    #pragma unroll
    for (int j = 0; j < 4; j++)
        #pragma unroll
        for (int c = 0; c < 2; c++) {
            int nc = nw * 32 + j * 8 + 2 * (lane & 3) + c;
            bb[j][c] = __ldg(&be1[nc]);
            ww[j][c] = __ldg(&We2[nc]);
        }
    float be2v = be2[0];

    int el = tid >> 1, q = tid & 1;        // staging: 2 threads / edge
    uint32_t AhAddr = smem_u32(AhB), AlAddr = smem_u32(AlB);
    uint32_t mrow = (uint32_t)(mw * 32 + (lane & 15)) * ROWB + (lane >> 4) * 16;

    for (int tile = blockIdx.x; tile < ETILES; tile += gridDim.x) {
        int e0 = tile * ET;
        // ---- stage A' (hi/lo) ----
        {
            int s = src[e0 + el], d = dst[e0 + el];
            const float4* hsP =
                reinterpret_cast<const float4*>(H + (size_t)s * 64 + q * 32);
            const float4* hdP =
                reinterpret_cast<const float4*>(H + (size_t)d * 64 + q * 32);
            char* rAh = AhB + el * ROWB;
            char* rAl = AlB + el * ROWB;
            #pragma unroll
            for (int c = 0; c < 4; c++) {
                float4 a0 = hsP[2 * c], a1 = hsP[2 * c + 1];
                float4 b0 = hdP[2 * c], b1 = hdP[2 * c + 1];
                float hs8[8] = {a0.x, a0.y, a0.z, a0.w, a1.x, a1.y, a1.z, a1.w};
                float hd8[8] = {b0.x, b0.y, b0.z, b0.w, b1.x, b1.y, b1.z, b1.w};
                float p8[8], q8[8];
                #pragma unroll
                for (int i = 0; i < 8; i++) {
                    p8[i] = hs8[i] * hd8[i];
                    q8[i] = fabsf(hs8[i] - hd8[i]);
                }
                int kb = (32 * q + 8 * c) * 2;
                write8(rAh, rAl, kb, hs8);
                write8(rAh, rAl, kb + 128, hd8);   // +64 halfs
                write8(rAh, rAl, kb + 256, p8);    // +128
                write8(rAh, rAl, kb + 384, q8);    // +192
            }
        }
        __syncthreads();

        // ---- MMA: K=256, 2 passes (Ah then Al), same Bh regs ----
        float dacc[2][4][4];
        #pragma unroll
        for (int t = 0; t < 2; t++)
            #pragma unroll
            for (int j = 0; j < 4; j++)
                #pragma unroll
                for (int r = 0; r < 4; r++) dacc[t][j][r] = 0.0f;

        #pragma unroll
        for (int pass = 0; pass < 2; pass++) {
            uint32_t base = (pass ? AlAddr : AhAddr) + mrow;
            #pragma unroll
            for (int s = 0; s < 16; s++) {
                uint32_t a0[4], a1[4];
                LDSM4(a0, base + s * 32);
                LDSM4(a1, base + 16 * ROWB + s * 32);
                #pragma unroll
                for (int j = 0; j < 4; j++) {
                    MMA16816(dacc[0][j], a0, bF[s][j]);
                    MMA16816(dacc[1][j], a1, bF[s][j]);
                }
            }
        }

        // ---- epilogue: relu(D+be1).We2, quad reduce, smem combine ----
        #pragma unroll
        for (int t = 0; t < 2; t++) {
            float p0 = 0.0f, p1 = 0.0f;
            #pragma unroll
            for (int j = 0; j < 4; j++) {
                p0 += fmaxf(dacc[t][j][0] + bb[j][0], 0.0f) * ww[j][0];
                p0 += fmaxf(dacc[t][j][1] + bb[j][1], 0.0f) * ww[j][1];
                p1 += fmaxf(dacc[t][j][2] + bb[j][0], 0.0f) * ww[j][0];
                p1 += fmaxf(dacc[t][j][3] + bb[j][1], 0.0f) * ww[j][1];
            }
            p0 += __shfl_xor_sync(0xffffffffu, p0, 1);
            p0 += __shfl_xor_sync(0xffffffffu, p0, 2);
            p1 += __shfl_xor_sync(0xffffffffu, p1, 1);
            p1 += __shfl_xor_sync(0xffffffffu, p1, 2);
            if ((lane & 3) == 0) {
                int r = mw * 32 + 16 * t + (lane >> 2);
                sred[r + 128 * nw]     = p0;
                sred[r + 8 + 128 * nw] = p1;
            }
        }
        __syncthreads();
        if (tid < 128) {
            float l = sred[tid] + sred[tid + 128] + be2v;
            logits[e0 + tid] = l;
            probs[e0 + tid]  = 1.0f / (1.0f + expf(-l));
        }
        __syncthreads();   // sred reads done before next tile's epilogue
    }
}

// ======================= launcher =======================
extern "C" void kernel_launch(void* const* d_in, const int* in_sizes, int n_in,
                              void* d_out, int out_size) {
    const float* x   = (const float*)d_in[0];
    const float* W1  = (const float*)d_in[1];
    const float* b1  = (const float*)d_in[2];
    const float* W2  = (const float*)d_in[3];
    const float* b2  = (const float*)d_in[4];
    const float* We1 = (const float*)d_in[5];
    const float* be1 = (const float*)d_in[6];
    const float* We2 = (const float*)d_in[7];
    const float* be2 = (const float*)d_in[8];
    const int*   ei  = (const int*)d_in[9];
    const int* src = ei;
    const int* dst = ei + NE;

    float* out    = (float*)d_out;
    float* H      = out;                 // [NN, 64]
    float* logits = out + NN * HID;      // [NE]
    float* probs  = logits + NE;         // [NE]

    void *yp, *h1p, *y2p, *zp;
    cudaGetSymbolAddress(&yp, g_y);
    cudaGetSymbolAddress(&h1p, g_h1);
    cudaGetSymbolAddress(&y2p, g_y2);
    cudaGetSymbolAddress(&zp, g_zeros);

    // CSR build
    k_zero<<<(NN + 255) / 256, 256>>>();
    k_count<<<(NE + 255) / 256, 256>>>(dst);
    k_scan<<<1, 1024>>>();
    k_bucket<<<(NE + 255) / 256, 256>>>(src, dst);

    // encoder layer 1 (GEMM first, then 64-dim aggregation; linearity commute)
    k_gemm<INDIM, HID><<<NN / 8, HID>>>(x, W1, (const float*)zp, (float*)yp);
    k_aggr<<<NN / 4, 256>>>((const float*)yp, b1, (float*)h1p);
    // encoder layer 2 -> H into d_out
    k_gemm<HID, HID><<<NN / 8, HID>>>((const float*)h1p, W2, (const float*)zp,
                                      (float*)y2p);
    k_aggr<<<NN / 4, 256>>>((const float*)y2p, b2, H);

    // fused edge MLP on tensor cores (mma.sync)
    cudaFuncSetAttribute(k_edge, cudaFuncAttributeMaxDynamicSharedMemorySize,
                         SMEM_EDGE);
    k_edge<<<148, 256, SMEM_EDGE>>>(H, src, dst, We1, be1, We2, be2,
                                    logits, probs);
}

// round 6
// speedup vs baseline: 2.8159x; 1.1370x over previous
#include <cuda_runtime.h>
#include <cuda_fp16.h>
#include <cstdint>
#include <math.h>

#define NN 50000
#define NE 800000
#define INDIM 128
#define HID 64

// ======================= device scratch =======================
__device__ int   g_deg[NN];
__device__ int   g_row_start[NN + 1];
__device__ int   g_cursor[NN];
__device__ int   g_csr[NE];
__device__ float g_invdeg[NN];
__device__ float g_y[NN * HID];
__device__ float g_h1[NN * HID];
__device__ float g_y2[NN * HID];
__device__ float g_zeros[128];

// ======================= CSR build =======================
__global__ void k_zero() {
    int i = blockIdx.x * blockDim.x + threadIdx.x;
    if (i < NN) g_deg[i] = 0;
}

__global__ void k_count(const int* __restrict__ dst) {
    int e = blockIdx.x * blockDim.x + threadIdx.x;
    if (e < NE) atomicAdd(&g_deg[dst[e]], 1);
}

__global__ void k_scan() {
    __shared__ int wsum[32];
    __shared__ int carry;
    int tid = threadIdx.x;
    if (tid == 0) carry = 0;
    __syncthreads();
    for (int base = 0; base < NN; base += 1024) {
        int i = base + tid;
        int v = (i < NN) ? g_deg[i] : 0;
        int xv = v;
        #pragma unroll
        for (int o = 1; o < 32; o <<= 1) {
            int y = __shfl_up_sync(0xffffffffu, xv, o);
            if ((tid & 31) >= o) xv += y;
        }
        if ((tid & 31) == 31) wsum[tid >> 5] = xv;
        __syncthreads();
        if (tid < 32) {
            int s = wsum[tid];
            #pragma unroll
            for (int o = 1; o < 32; o <<= 1) {
                int y = __shfl_up_sync(0xffffffffu, s, o);
                if (tid >= o) s += y;
            }
            wsum[tid] = s;
        }
        __syncthreads();
        int add = (tid >= 32) ? wsum[(tid >> 5) - 1] : 0;
        int incl = xv + add + carry;
        if (i < NN) {
            g_row_start[i] = incl - v;
            g_cursor[i]    = incl - v;
            g_invdeg[i]    = 1.0f / fmaxf((float)v, 1.0f);
        }
        __syncthreads();
        if (tid == 1023) carry = incl;
        __syncthreads();
    }
    if (tid == 0) g_row_start[NN] = carry;
}

__global__ void k_bucket(const int* __restrict__ src, const int* __restrict__ dst) {
    int e = blockIdx.x * blockDim.x + threadIdx.x;
    if (e < NE) {
        int d = dst[e];
        int p = atomicAdd(&g_cursor[d], 1);
        g_csr[p] = src[e];
    }
}

// ======= mean aggregation (fused bias + relu): out = relu(y + agg(y)/deg + b)
__global__ void __launch_bounds__(256) k_aggr(const float* __restrict__ y,
                                              const float* __restrict__ bias,
                                              float* __restrict__ out) {
    int node = blockIdx.x * 4 + (threadIdx.x >> 6);
    int k = threadIdx.x & 63;
    int beg = g_row_start[node], end = g_row_start[node + 1];
    float acc = 0.0f;
    int e = beg;
    for (; e + 3 < end; e += 4) {
        int s0 = __ldg(&g_csr[e]);
        int s1 = __ldg(&g_csr[e + 1]);
        int s2 = __ldg(&g_csr[e + 2]);
        int s3 = __ldg(&g_csr[e + 3]);
        float v0 = __ldg(&y[s0 * 64 + k]);
        float v1 = __ldg(&y[s1 * 64 + k]);
        float v2 = __ldg(&y[s2 * 64 + k]);
        float v3 = __ldg(&y[s3 * 64 + k]);
        acc += (v0 + v1) + (v2 + v3);
    }
    for (; e < end; e++) acc += __ldg(&y[__ldg(&g_csr[e]) * 64 + k]);
    float v = y[node * 64 + k] + acc * g_invdeg[node] + bias[k];
    out[node * 64 + k] = fmaxf(v, 0.0f);
}

// ============ dense GEMM: out = Z @ W + bias; NC=64 cols, 40 rows/block ============
// Shared memory is DYNAMIC (exceeds 48KB static limit at K=128).
#define GRT 40
#define GNT 320
template <int K>
__global__ void __launch_bounds__(GNT) k_gemm(const float* __restrict__ Z,
                                              const float* __restrict__ W,
                                              const float* __restrict__ bias,
                                              float* __restrict__ out) {
    constexpr int KP = K + 4;
    extern __shared__ float smg[];
    float* Ws = smg;                 // [64 * KP]
    float* Zs = smg + 64 * KP;       // [GRT * KP]
    int tid = threadIdx.x;
    int j = tid % 64, rg = tid / 64;   // rg in 0..4
    for (int idx = tid; idx < K * 64; idx += GNT) {
        int k = idx >> 6, c = idx & 63;
        Ws[c * KP + k] = W[idx];
    }
    int row0 = blockIdx.x * GRT;
    for (int idx = tid; idx < GRT * (K / 4); idx += GNT) {
        int r = idx / (K / 4), kq = idx % (K / 4);
        float4 v = reinterpret_cast<const float4*>(Z + (size_t)(row0 + r) * K)[kq];
        *reinterpret_cast<float4*>(&Zs[r * KP + kq * 4]) = v;
    }
    __syncthreads();
    float bj = bias[j];
    float acc[8];
    #pragma unroll
    for (int r = 0; r < 8; r++) acc[r] = bj;
    const float4* w4 = reinterpret_cast<const float4*>(&Ws[j * KP]);
    #pragma unroll 8
    for (int k4 = 0; k4 < K / 4; k4++) {
        float4 w = w4[k4];
        #pragma unroll
        for (int r = 0; r < 8; r++) {
            float4 z = *reinterpret_cast<const float4*>(&Zs[(rg * 8 + r) * KP + k4 * 4]);
            acc[r] += z.x * w.x;
            acc[r] += z.y * w.y;
            acc[r] += z.z * w.z;
            acc[r] += z.w * w.w;
        }
    }
    #pragma unroll
    for (int r = 0; r < 8; r++)
        out[(size_t)(row0 + rg * 8 + r) * 64 + j] = acc[r];
}

// ======================= fused edge MLP on mma.sync (HMMA.16816) =======================
// Per 128-edge tile: A'[128 x 256] = [hs|hd|p|q] split fp16 hi/lo in smem.
// B = fp16(We1) [256 x 64] held in REGISTERS (per-warp fragments), loaded once.
// D (fp32) = Ah*Bh + Al*Bh = A*Bh exactly; only B quantization error (~1.2e-4).
#define ET 128
#define ETILES (NE / ET)         // 6250
#define ROWB 528                 // 264 halfs per A row (8-half pad)
#define OFF_AH 1024
#define OFF_AL (OFF_AH + 128 * ROWB)
#define SMEM_EDGE (OFF_AL + 128 * ROWB)

__device__ __forceinline__ uint32_t smem_u32(const void* p) {
    uint32_t a;
    asm("{ .reg .u64 t; cvta.to.shared.u64 t, %1; cvt.u32.u64 %0, t; }"
        : "=r"(a) : "l"(p));
    return a;
}

#define LDSM4(r, addr)                                                         \
    asm volatile("ldmatrix.sync.aligned.m8n8.x4.shared.b16 {%0,%1,%2,%3}, [%4];" \
                 : "=r"((r)[0]), "=r"((r)[1]), "=r"((r)[2]), "=r"((r)[3])      \
                 : "r"(addr))

#define MMA16816(d, a, b)                                                      \
    asm volatile("mma.sync.aligned.m16n8k16.row.col.f32.f16.f16.f32 "          \
                 "{%0,%1,%2,%3},{%4,%5,%6,%7},{%8,%9},{%0,%1,%2,%3};"          \
                 : "+f"((d)[0]), "+f"((d)[1]), "+f"((d)[2]), "+f"((d)[3])      \
                 : "r"((a)[0]), "r"((a)[1]), "r"((a)[2]), "r"((a)[3]),         \
                   "r"((b)[0]), "r"((b)[1]))

__device__ __forceinline__ void write8(char* ah, char* al, int koff2,
                                       const float* v) {
    uint32_t hi[4], lo[4];
    #pragma unroll
    for (int i = 0; i < 4; i++) {
        __half2 h = __floats2half2_rn(v[2 * i], v[2 * i + 1]);
        float2 hf = __half22float2(h);
        __half2 l = __floats2half2_rn(v[2 * i] - hf.x, v[2 * i + 1] - hf.y);
        hi[i] = *reinterpret_cast<uint32_t*>(&h);
        lo[i] = *reinterpret_cast<uint32_t*>(&l);
    }
    *reinterpret_cast<uint4*>(ah + koff2) = make_uint4(hi[0], hi[1], hi[2], hi[3]);
    *reinterpret_cast<uint4*>(al + koff2) = make_uint4(lo[0], lo[1], lo[2], lo[3]);
}

__global__ void __launch_bounds__(256, 1) k_edge(
    const float* __restrict__ H, const int* __restrict__ src,
    const int* __restrict__ dst, const float* __restrict__ We1,
    const float* __restrict__ be1, const float* __restrict__ We2,
    const float* __restrict__ be2,
    float* __restrict__ logits, float* __restrict__ probs) {
    extern __shared__ char sm[];
    float* sred = reinterpret_cast<float*>(sm);       // 256 floats
    char* AhB = sm + OFF_AH;
    char* AlB = sm + OFF_AL;

    int tid = threadIdx.x, lane = tid & 31, wid = tid >> 5;
    int mw = wid & 3, nw = wid >> 2;

    // ---- load B fragments into registers (once per block) ----
    uint32_t bF[16][4][2];
    #pragma unroll
    for (int s = 0; s < 16; s++)
        #pragma unroll
        for (int j = 0; j < 4; j++)
            #pragma unroll
            for (int r = 0; r < 2; r++) {
                int k = s * 16 + 2 * (lane & 3) + r * 8;
                int n = nw * 32 + j * 8 + (lane >> 2);
                __half2 h = __floats2half2_rn(__ldg(&We1[k * 64 + n]),
                                              __ldg(&We1[(k + 1) * 64 + n]));
                bF[s][j][r] = *reinterpret_cast<uint32_t*>(&h);
            }
    float bb[4][2], ww[4][2];
    #pragma unroll
    for (int j = 0; j < 4; j++)
        #pragma unroll
        for (int c = 0; c < 2; c++) {
            int nc = nw * 32 + j * 8 + 2 * (lane & 3) + c;
            bb[j][c] = __ldg(&be1[nc]);
            ww[j][c] = __ldg(&We2[nc]);
        }
    float be2v = be2[0];

    int el = tid >> 1, q = tid & 1;        // staging: 2 threads / edge
    uint32_t AhAddr = smem_u32(AhB), AlAddr = smem_u32(AlB);
    uint32_t mrow = (uint32_t)(mw * 32 + (lane & 15)) * ROWB + (lane >> 4) * 16;

    for (int tile = blockIdx.x; tile < ETILES; tile += gridDim.x) {
        int e0 = tile * ET;
        // ---- stage A' (hi/lo) ----
        {
            int s = src[e0 + el], d = dst[e0 + el];
            const float4* hsP =
                reinterpret_cast<const float4*>(H + (size_t)s * 64 + q * 32);
            const float4* hdP =
                reinterpret_cast<const float4*>(H + (size_t)d * 64 + q * 32);
            char* rAh = AhB + el * ROWB;
            char* rAl = AlB + el * ROWB;
            #pragma unroll
            for (int c = 0; c < 4; c++) {
                float4 a0 = hsP[2 * c], a1 = hsP[2 * c + 1];
                float4 b0 = hdP[2 * c], b1 = hdP[2 * c + 1];
                float hs8[8] = {a0.x, a0.y, a0.z, a0.w, a1.x, a1.y, a1.z, a1.w};
                float hd8[8] = {b0.x, b0.y, b0.z, b0.w, b1.x, b1.y, b1.z, b1.w};
                float p8[8], q8[8];
                #pragma unroll
                for (int i = 0; i < 8; i++) {
                    p8[i] = hs8[i] * hd8[i];
                    q8[i] = fabsf(hs8[i] - hd8[i]);
                }
                int kb = (32 * q + 8 * c) * 2;
                write8(rAh, rAl, kb, hs8);
                write8(rAh, rAl, kb + 128, hd8);
                write8(rAh, rAl, kb + 256, p8);
                write8(rAh, rAl, kb + 384, q8);
            }
        }
        __syncthreads();

        // ---- MMA: K=256, 2 passes (Ah then Al), same Bh regs ----
        float dacc[2][4][4];
        #pragma unroll
        for (int t = 0; t < 2; t++)
            #pragma unroll
            for (int j = 0; j < 4; j++)
                #pragma unroll
                for (int r = 0; r < 4; r++) dacc[t][j][r] = 0.0f;

        #pragma unroll
        for (int pass = 0; pass < 2; pass++) {
            uint32_t base = (pass ? AlAddr : AhAddr) + mrow;
            #pragma unroll
            for (int s = 0; s < 16; s++) {
                uint32_t a0[4], a1[4];
                LDSM4(a0, base + s * 32);
                LDSM4(a1, base + 16 * ROWB + s * 32);
                #pragma unroll
                for (int j = 0; j < 4; j++) {
                    MMA16816(dacc[0][j], a0, bF[s][j]);
                    MMA16816(dacc[1][j], a1, bF[s][j]);
                }
            }
        }

        // ---- epilogue: relu(D+be1).We2, quad reduce, smem combine ----
        #pragma unroll
        for (int t = 0; t < 2; t++) {
            float p0 = 0.0f, p1 = 0.0f;
            #pragma unroll
            for (int j = 0; j < 4; j++) {
                p0 += fmaxf(dacc[t][j][0] + bb[j][0], 0.0f) * ww[j][0];
                p0 += fmaxf(dacc[t][j][1] + bb[j][1], 0.0f) * ww[j][1];
                p1 += fmaxf(dacc[t][j][2] + bb[j][0], 0.0f) * ww[j][0];
                p1 += fmaxf(dacc[t][j][3] + bb[j][1], 0.0f) * ww[j][1];
            }
            p0 += __shfl_xor_sync(0xffffffffu, p0, 1);
            p0 += __shfl_xor_sync(0xffffffffu, p0, 2);
            p1 += __shfl_xor_sync(0xffffffffu, p1, 1);
            p1 += __shfl_xor_sync(0xffffffffu, p1, 2);
            if ((lane & 3) == 0) {
                int r = mw * 32 + 16 * t + (lane >> 2);
                sred[r + 128 * nw]     = p0;
                sred[r + 8 + 128 * nw] = p1;
            }
        }
        __syncthreads();
        if (tid < 128) {
            float l = sred[tid] + sred[tid + 128] + be2v;
            logits[e0 + tid] = l;
            probs[e0 + tid]  = 1.0f / (1.0f + expf(-l));
        }
        __syncthreads();
    }
}

// ======================= launcher =======================
extern "C" void kernel_launch(void* const* d_in, const int* in_sizes, int n_in,
                              void* d_out, int out_size) {
    const float* x   = (const float*)d_in[0];
    const float* W1  = (const float*)d_in[1];
    const float* b1  = (const float*)d_in[2];
    const float* W2  = (const float*)d_in[3];
    const float* b2  = (const float*)d_in[4];
    const float* We1 = (const float*)d_in[5];
    const float* be1 = (const float*)d_in[6];
    const float* We2 = (const float*)d_in[7];
    const float* be2 = (const float*)d_in[8];
    const int*   ei  = (const int*)d_in[9];
    const int* src = ei;
    const int* dst = ei + NE;

    float* out    = (float*)d_out;
    float* H      = out;                 // [NN, 64]
    float* logits = out + NN * HID;      // [NE]
    float* probs  = logits + NE;         // [NE]

    void *yp, *h1p, *y2p, *zp;
    cudaGetSymbolAddress(&yp, g_y);
    cudaGetSymbolAddress(&h1p, g_h1);
    cudaGetSymbolAddress(&y2p, g_y2);
    cudaGetSymbolAddress(&zp, g_zeros);

    // CSR build
    k_zero<<<(NN + 255) / 256, 256>>>();
    k_count<<<(NE + 255) / 256, 256>>>(dst);
    k_scan<<<1, 1024>>>();
    k_bucket<<<(NE + 255) / 256, 256>>>(src, dst);

    // dynamic smem sizes for the gemms
    int sm128 = (64 * (INDIM + 4) + GRT * (INDIM + 4)) * (int)sizeof(float);
    int sm64  = (64 * (HID + 4)   + GRT * (HID + 4))   * (int)sizeof(float);
    cudaFuncSetAttribute(k_gemm<INDIM>,
                         cudaFuncAttributeMaxDynamicSharedMemorySize, sm128);
    cudaFuncSetAttribute(k_gemm<HID>,
                         cudaFuncAttributeMaxDynamicSharedMemorySize, sm64);

    // encoder layer 1 (GEMM first, then 64-dim aggregation; linearity commute)
    k_gemm<INDIM><<<NN / GRT, GNT, sm128>>>(x, W1, (const float*)zp, (float*)yp);
    k_aggr<<<NN / 4, 256>>>((const float*)yp, b1, (float*)h1p);
    // encoder layer 2 -> H into d_out
    k_gemm<HID><<<NN / GRT, GNT, sm64>>>((const float*)h1p, W2, (const float*)zp,
                                         (float*)y2p);
    k_aggr<<<NN / 4, 256>>>((const float*)y2p, b2, H);

    // fused edge MLP on tensor cores (mma.sync)
    cudaFuncSetAttribute(k_edge, cudaFuncAttributeMaxDynamicSharedMemorySize,
                         SMEM_EDGE);
    k_edge<<<148, 256, SMEM_EDGE>>>(H, src, dst, We1, be1, We2, be2,
                                    logits, probs);
}

// round 7
// speedup vs baseline: 3.4621x; 1.2295x over previous
#include <cuda_runtime.h>
#include <cuda_fp16.h>
#include <cstdint>
#include <math.h>

#define NN 50000
#define NE 800000
#define INDIM 128
#define HID 64

// ======================= device scratch =======================
__device__ int   g_deg[NN];
__device__ int   g_row_start[NN + 1];
__device__ int   g_cursor[NN];
__device__ int   g_csr[NE];
__device__ float g_invdeg[NN];
__device__ float g_y[NN * HID];
__device__ float g_h1[NN * HID];
__device__ float g_y2[NN * HID];
__device__ float g_zeros[128];

// ======================= CSR build =======================
__global__ void k_zero() {
    int i = blockIdx.x * blockDim.x + threadIdx.x;
    if (i < NN) g_deg[i] = 0;
}

__global__ void k_count(const int* __restrict__ dst) {
    int e = blockIdx.x * blockDim.x + threadIdx.x;
    if (e < NE) atomicAdd(&g_deg[dst[e]], 1);
}

__global__ void k_scan() {
    __shared__ int wsum[32];
    __shared__ int carry;
    int tid = threadIdx.x;
    if (tid == 0) carry = 0;
    __syncthreads();
    for (int base = 0; base < NN; base += 1024) {
        int i = base + tid;
        int v = (i < NN) ? g_deg[i] : 0;
        int xv = v;
        #pragma unroll
        for (int o = 1; o < 32; o <<= 1) {
            int y = __shfl_up_sync(0xffffffffu, xv, o);
            if ((tid & 31) >= o) xv += y;
        }
        if ((tid & 31) == 31) wsum[tid >> 5] = xv;
        __syncthreads();
        if (tid < 32) {
            int s = wsum[tid];
            #pragma unroll
            for (int o = 1; o < 32; o <<= 1) {
                int y = __shfl_up_sync(0xffffffffu, s, o);
                if (tid >= o) s += y;
            }
            wsum[tid] = s;
        }
        __syncthreads();
        int add = (tid >= 32) ? wsum[(tid >> 5) - 1] : 0;
        int incl = xv + add + carry;
        if (i < NN) {
            g_row_start[i] = incl - v;
            g_cursor[i]    = incl - v;
            g_invdeg[i]    = 1.0f / fmaxf((float)v, 1.0f);
        }
        __syncthreads();
        if (tid == 1023) carry = incl;
        __syncthreads();
    }
    if (tid == 0) g_row_start[NN] = carry;
}

__global__ void k_bucket(const int* __restrict__ src, const int* __restrict__ dst) {
    int e = blockIdx.x * blockDim.x + threadIdx.x;
    if (e < NE) {
        int d = dst[e];
        int p = atomicAdd(&g_cursor[d], 1);
        g_csr[p] = src[e];
    }
}

// ======= mean aggregation (fused bias + relu): out = relu(y + agg(y)/deg + b)
// 16 threads per node, float4 per thread, 4-neighbor unroll.
__global__ void __launch_bounds__(256) k_aggr(const float* __restrict__ y,
                                              const float* __restrict__ bias,
                                              float* __restrict__ out) {
    int node = blockIdx.x * 16 + (threadIdx.x >> 4);
    int c4 = (threadIdx.x & 15) * 4;
    int beg = g_row_start[node], end = g_row_start[node + 1];
    float4 acc = make_float4(0.f, 0.f, 0.f, 0.f);
    int e = beg;
    for (; e + 3 < end; e += 4) {
        int s0 = __ldg(&g_csr[e]);
        int s1 = __ldg(&g_csr[e + 1]);
        int s2 = __ldg(&g_csr[e + 2]);
        int s3 = __ldg(&g_csr[e + 3]);
        float4 v0 = *reinterpret_cast<const float4*>(y + (size_t)s0 * 64 + c4);
        float4 v1 = *reinterpret_cast<const float4*>(y + (size_t)s1 * 64 + c4);
        float4 v2 = *reinterpret_cast<const float4*>(y + (size_t)s2 * 64 + c4);
        float4 v3 = *reinterpret_cast<const float4*>(y + (size_t)s3 * 64 + c4);
        acc.x += (v0.x + v1.x) + (v2.x + v3.x);
        acc.y += (v0.y + v1.y) + (v2.y + v3.y);
        acc.z += (v0.z + v1.z) + (v2.z + v3.z);
        acc.w += (v0.w + v1.w) + (v2.w + v3.w);
    }
    for (; e < end; e++) {
        int s = __ldg(&g_csr[e]);
        float4 v = *reinterpret_cast<const float4*>(y + (size_t)s * 64 + c4);
        acc.x += v.x; acc.y += v.y; acc.z += v.z; acc.w += v.w;
    }
    float inv = g_invdeg[node];
    float4 self = *reinterpret_cast<const float4*>(y + (size_t)node * 64 + c4);
    float4 b = *reinterpret_cast<const float4*>(bias + c4);
    float4 r;
    r.x = fmaxf(self.x + acc.x * inv + b.x, 0.0f);
    r.y = fmaxf(self.y + acc.y * inv + b.y, 0.0f);
    r.z = fmaxf(self.z + acc.z * inv + b.z, 0.0f);
    r.w = fmaxf(self.w + acc.w * inv + b.w, 0.0f);
    *reinterpret_cast<float4*>(out + (size_t)node * 64 + c4) = r;
}

// ============ dense GEMM: out = Z @ W + bias; NC=64 cols, 40 rows/block ============
#define GRT 40
#define GNT 320
template <int K>
__global__ void __launch_bounds__(GNT) k_gemm(const float* __restrict__ Z,
                                              const float* __restrict__ W,
                                              const float* __restrict__ bias,
                                              float* __restrict__ out) {
    constexpr int KP = K + 4;
    extern __shared__ float smg[];
    float* Ws = smg;                 // [64 * KP]
    float* Zs = smg + 64 * KP;       // [GRT * KP]
    int tid = threadIdx.x;
    int j = tid % 64, rg = tid / 64;   // rg in 0..4
    for (int idx = tid; idx < K * 64; idx += GNT) {
        int k = idx >> 6, c = idx & 63;
        Ws[c * KP + k] = W[idx];
    }
    int row0 = blockIdx.x * GRT;
    for (int idx = tid; idx < GRT * (K / 4); idx += GNT) {
        int r = idx / (K / 4), kq = idx % (K / 4);
        float4 v = reinterpret_cast<const float4*>(Z + (size_t)(row0 + r) * K)[kq];
        *reinterpret_cast<float4*>(&Zs[r * KP + kq * 4]) = v;
    }
    __syncthreads();
    float bj = bias[j];
    float acc[8];
    #pragma unroll
    for (int r = 0; r < 8; r++) acc[r] = bj;
    const float4* w4 = reinterpret_cast<const float4*>(&Ws[j * KP]);
    #pragma unroll 8
    for (int k4 = 0; k4 < K / 4; k4++) {
        float4 w = w4[k4];
        #pragma unroll
        for (int r = 0; r < 8; r++) {
            float4 z = *reinterpret_cast<const float4*>(&Zs[(rg * 8 + r) * KP + k4 * 4]);
            acc[r] += z.x * w.x;
            acc[r] += z.y * w.y;
            acc[r] += z.z * w.z;
            acc[r] += z.w * w.w;
        }
    }
    #pragma unroll
    for (int r = 0; r < 8; r++)
        out[(size_t)(row0 + rg * 8 + r) * 64 + j] = acc[r];
}

// ======================= fused edge MLP on mma.sync (HMMA.16816) =======================
// Per 128-edge tile: A'[128 x 256] = [hs|hd|p|q] in fp16 (single precision pass).
// B = fp16(We1) [256 x 64] held in REGISTERS (per-warp fragments), loaded once.
// Error: fp16 quantization of both A and B, ~2-4e-4 normwise (threshold 1e-3).
#define ET 128
#define ETILES (NE / ET)         // 6250
#define ROWB 528                 // 264 halfs per A row (8-half pad)
#define OFF_AH 1024
#define SMEM_EDGE (OFF_AH + 128 * ROWB)   // 68608 bytes

__device__ __forceinline__ uint32_t smem_u32(const void* p) {
    uint32_t a;
    asm("{ .reg .u64 t; cvta.to.shared.u64 t, %1; cvt.u32.u64 %0, t; }"
        : "=r"(a) : "l"(p));
    return a;
}

#define LDSM4(r, addr)                                                         \
    asm volatile("ldmatrix.sync.aligned.m8n8.x4.shared.b16 {%0,%1,%2,%3}, [%4];" \
                 : "=r"((r)[0]), "=r"((r)[1]), "=r"((r)[2]), "=r"((r)[3])      \
                 : "r"(addr))

#define MMA16816(d, a, b)                                                      \
    asm volatile("mma.sync.aligned.m16n8k16.row.col.f32.f16.f16.f32 "          \
                 "{%0,%1,%2,%3},{%4,%5,%6,%7},{%8,%9},{%0,%1,%2,%3};"          \
                 : "+f"((d)[0]), "+f"((d)[1]), "+f"((d)[2]), "+f"((d)[3])      \
                 : "r"((a)[0]), "r"((a)[1]), "r"((a)[2]), "r"((a)[3]),         \
                   "r"((b)[0]), "r"((b)[1]))

__device__ __forceinline__ void write8h(char* ah, int koff2, const float* v) {
    uint32_t hi[4];
    #pragma unroll
    for (int i = 0; i < 4; i++) {
        __half2 h = __floats2half2_rn(v[2 * i], v[2 * i + 1]);
        hi[i] = *reinterpret_cast<uint32_t*>(&h);
    }
    *reinterpret_cast<uint4*>(ah + koff2) = make_uint4(hi[0], hi[1], hi[2], hi[3]);
}

__global__ void __launch_bounds__(256, 1) k_edge(
    const float* __restrict__ H, const int* __restrict__ src,
    const int* __restrict__ dst, const float* __restrict__ We1,
    const float* __restrict__ be1, const float* __restrict__ We2,
    const float* __restrict__ be2,
    float* __restrict__ logits, float* __restrict__ probs) {
    extern __shared__ char sm[];
    float* sred = reinterpret_cast<float*>(sm);       // 256 floats
    char* AhB = sm + OFF_AH;

    int tid = threadIdx.x, lane = tid & 31, wid = tid >> 5;
    int mw = wid & 3, nw = wid >> 2;

    // ---- load B fragments into registers (once per block) ----
    uint32_t bF[16][4][2];
    #pragma unroll
    for (int s = 0; s < 16; s++)
        #pragma unroll
        for (int j = 0; j < 4; j++)
            #pragma unroll
            for (int r = 0; r < 2; r++) {
                int k = s * 16 + 2 * (lane & 3) + r * 8;
                int n = nw * 32 + j * 8 + (lane >> 2);
                __half2 h = __floats2half2_rn(__ldg(&We1[k * 64 + n]),
                                              __ldg(&We1[(k + 1) * 64 + n]));
                bF[s][j][r] = *reinterpret_cast<uint32_t*>(&h);
            }
    float bb[4][2], ww[4][2];
    #pragma unroll
    for (int j = 0; j < 4; j++)
        #pragma unroll
        for (int c = 0; c < 2; c++) {
            int nc = nw * 32 + j * 8 + 2 * (lane & 3) + c;
            bb[j][c] = __ldg(&be1[nc]);
            ww[j][c] = __ldg(&We2[nc]);
        }
    float be2v = be2[0];

    int el = tid >> 1, q = tid & 1;        // staging: 2 threads / edge
    uint32_t AhAddr = smem_u32(AhB);
    uint32_t mrow = (uint32_t)(mw * 32 + (lane & 15)) * ROWB + (lane >> 4) * 16;

    for (int tile = blockIdx.x; tile < ETILES; tile += gridDim.x) {
        int e0 = tile * ET;
        // ---- stage A' (fp16) ----
        {
            int s = src[e0 + el], d = dst[e0 + el];
            const float4* hsP =
                reinterpret_cast<const float4*>(H + (size_t)s * 64 + q * 32);
            const float4* hdP =
                reinterpret_cast<const float4*>(H + (size_t)d * 64 + q * 32);
            char* rAh = AhB + el * ROWB;
            #pragma unroll
            for (int c = 0; c < 4; c++) {
                float4 a0 = hsP[2 * c], a1 = hsP[2 * c + 1];
                float4 b0 = hdP[2 * c], b1 = hdP[2 * c + 1];
                float hs8[8] = {a0.x, a0.y, a0.z, a0.w, a1.x, a1.y, a1.z, a1.w};
                float hd8[8] = {b0.x, b0.y, b0.z, b0.w, b1.x, b1.y, b1.z, b1.w};
                float p8[8], q8[8];
                #pragma unroll
                for (int i = 0; i < 8; i++) {
                    p8[i] = hs8[i] * hd8[i];
                    q8[i] = fabsf(hs8[i] - hd8[i]);
                }
                int kb = (32 * q + 8 * c) * 2;
                write8h(rAh, kb, hs8);
                write8h(rAh, kb + 128, hd8);
                write8h(rAh, kb + 256, p8);
                write8h(rAh, kb + 384, q8);
            }
        }
        __syncthreads();

        // ---- MMA: K=256, single fp16 pass ----
        float dacc[2][4][4];
        #pragma unroll
        for (int t = 0; t < 2; t++)
            #pragma unroll
            for (int j = 0; j < 4; j++)
                #pragma unroll
                for (int r = 0; r < 4; r++) dacc[t][j][r] = 0.0f;

        uint32_t base = AhAddr + mrow;
        #pragma unroll
        for (int s = 0; s < 16; s++) {
            uint32_t a0[4], a1[4];
            LDSM4(a0, base + s * 32);
            LDSM4(a1, base + 16 * ROWB + s * 32);
            #pragma unroll
            for (int j = 0; j < 4; j++) {
                MMA16816(dacc[0][j], a0, bF[s][j]);
                MMA16816(dacc[1][j], a1, bF[s][j]);
            }
        }

        // ---- epilogue: relu(D+be1).We2, quad reduce, smem combine ----
        #pragma unroll
        for (int t = 0; t < 2; t++) {
            float p0 = 0.0f, p1 = 0.0f;
            #pragma unroll
            for (int j = 0; j < 4; j++) {
                p0 += fmaxf(dacc[t][j][0] + bb[j][0], 0.0f) * ww[j][0];
                p0 += fmaxf(dacc[t][j][1] + bb[j][1], 0.0f) * ww[j][1];
                p1 += fmaxf(dacc[t][j][2] + bb[j][0], 0.0f) * ww[j][0];
                p1 += fmaxf(dacc[t][j][3] + bb[j][1], 0.0f) * ww[j][1];
            }
            p0 += __shfl_xor_sync(0xffffffffu, p0, 1);
            p0 += __shfl_xor_sync(0xffffffffu, p0, 2);
            p1 += __shfl_xor_sync(0xffffffffu, p1, 1);
            p1 += __shfl_xor_sync(0xffffffffu, p1, 2);
            if ((lane & 3) == 0) {
                int r = mw * 32 + 16 * t + (lane >> 2);
                sred[r + 128 * nw]     = p0;
                sred[r + 8 + 128 * nw] = p1;
            }
        }
        __syncthreads();
        if (tid < 128) {
            float l = sred[tid] + sred[tid + 128] + be2v;
            logits[e0 + tid] = l;
            probs[e0 + tid]  = 1.0f / (1.0f + expf(-l));
        }
        __syncthreads();
    }
}

// ======================= launcher =======================
extern "C" void kernel_launch(void* const* d_in, const int* in_sizes, int n_in,
                              void* d_out, int out_size) {
    const float* x   = (const float*)d_in[0];
    const float* W1  = (const float*)d_in[1];
    const float* b1  = (const float*)d_in[2];
    const float* W2  = (const float*)d_in[3];
    const float* b2  = (const float*)d_in[4];
    const float* We1 = (const float*)d_in[5];
    const float* be1 = (const float*)d_in[6];
    const float* We2 = (const float*)d_in[7];
    const float* be2 = (const float*)d_in[8];
    const int*   ei  = (const int*)d_in[9];
    const int* src = ei;
    const int* dst = ei + NE;

    float* out    = (float*)d_out;
    float* H      = out;                 // [NN, 64]
    float* logits = out + NN * HID;      // [NE]
    float* probs  = logits + NE;         // [NE]

    void *yp, *h1p, *y2p, *zp;
    cudaGetSymbolAddress(&yp, g_y);
    cudaGetSymbolAddress(&h1p, g_h1);
    cudaGetSymbolAddress(&y2p, g_y2);
    cudaGetSymbolAddress(&zp, g_zeros);

    // CSR build
    k_zero<<<(NN + 255) / 256, 256>>>();
    k_count<<<(NE + 255) / 256, 256>>>(dst);
    k_scan<<<1, 1024>>>();
    k_bucket<<<(NE + 255) / 256, 256>>>(src, dst);

    // dynamic smem sizes for the gemms
    int sm128 = (64 * (INDIM + 4) + GRT * (INDIM + 4)) * (int)sizeof(float);
    int sm64  = (64 * (HID + 4)   + GRT * (HID + 4))   * (int)sizeof(float);
    cudaFuncSetAttribute(k_gemm<INDIM>,
                         cudaFuncAttributeMaxDynamicSharedMemorySize, sm128);
    cudaFuncSetAttribute(k_gemm<HID>,
                         cudaFuncAttributeMaxDynamicSharedMemorySize, sm64);

    // encoder layer 1 (GEMM first, then 64-dim aggregation; linearity commute)
    k_gemm<INDIM><<<NN / GRT, GNT, sm128>>>(x, W1, (const float*)zp, (float*)yp);
    k_aggr<<<NN / 16, 256>>>((const float*)yp, b1, (float*)h1p);
    // encoder layer 2 -> H into d_out
    k_gemm<HID><<<NN / GRT, GNT, sm64>>>((const float*)h1p, W2, (const float*)zp,
                                         (float*)y2p);
    k_aggr<<<NN / 16, 256>>>((const float*)y2p, b2, H);

    // fused edge MLP on tensor cores (mma.sync, single fp16 pass)
    cudaFuncSetAttribute(k_edge, cudaFuncAttributeMaxDynamicSharedMemorySize,
                         SMEM_EDGE);
    k_edge<<<148, 256, SMEM_EDGE>>>(H, src, dst, We1, be1, We2, be2,
                                    logits, probs);
}

// round 8
// speedup vs baseline: 3.7644x; 1.0873x over previous
#include <cuda_runtime.h>
#include <cuda_fp16.h>
#include <cstdint>
#include <math.h>

#define NN 50000
#define NE 800000
#define INDIM 128
#define HID 64
#define NSCH 49   // ceil(NN/1024)

// ======================= device scratch =======================
__device__ int   g_deg[NN];
__device__ int   g_row_start[NN + 1];
__device__ int   g_cursor[NN];
__device__ int   g_csr[NE];
__device__ float g_invdeg[NN];
__device__ int   g_psum[64];
__device__ int   g_poff[64];
__device__ float g_y[NN * HID];
__device__ float g_h1[NN * HID];
__device__ float g_y2[NN * HID];
__device__ float g_zeros[128];

// ======================= CSR build =======================
__global__ void k_zero() {
    int i = blockIdx.x * blockDim.x + threadIdx.x;
    if (i < NN) g_deg[i] = 0;
}

__global__ void k_count(const int* __restrict__ dst) {
    int e = blockIdx.x * blockDim.x + threadIdx.x;
    if (e < NE) atomicAdd(&g_deg[dst[e]], 1);
}

// Phase 1: per-chunk (1024) exclusive scan; chunk totals to g_psum.
__global__ void __launch_bounds__(1024) k_scan1() {
    __shared__ int wsum[32];
    int tid = threadIdx.x;
    int i = blockIdx.x * 1024 + tid;
    int v = (i < NN) ? g_deg[i] : 0;
    int xv = v;
    #pragma unroll
    for (int o = 1; o < 32; o <<= 1) {
        int y = __shfl_up_sync(0xffffffffu, xv, o);
        if ((tid & 31) >= o) xv += y;
    }
    if ((tid & 31) == 31) wsum[tid >> 5] = xv;
    __syncthreads();
    if (tid < 32) {
        int s = wsum[tid];
        #pragma unroll
        for (int o = 1; o < 32; o <<= 1) {
            int y = __shfl_up_sync(0xffffffffu, s, o);
            if (tid >= o) s += y;
        }
        wsum[tid] = s;
    }
    __syncthreads();
    int add = (tid >= 32) ? wsum[(tid >> 5) - 1] : 0;
    if (i < NN) g_row_start[i] = xv + add - v;   // exclusive within chunk
    if (tid == 0) g_psum[blockIdx.x] = wsum[31];
}

// Phase 2: scan the 49 chunk totals (single 64-thread block).
__global__ void k_scan2() {
    __shared__ int ws;
    int tid = threadIdx.x;   // 64
    int v = (tid < NSCH) ? g_psum[tid] : 0;
    int x = v;
    #pragma unroll
    for (int o = 1; o < 32; o <<= 1) {
        int y = __shfl_up_sync(0xffffffffu, x, o);
        if ((tid & 31) >= o) x += y;
    }
    if (tid == 31) ws = x;
    __syncthreads();
    int incl = x + ((tid >= 32) ? ws : 0);
    if (tid < NSCH) g_poff[tid] = incl - v;      // exclusive chunk offset
    if (tid == NSCH - 1) g_row_start[NN] = incl; // grand total (== NE)
}

// Phase 3: apply chunk offsets; init cursor and invdeg.
__global__ void __launch_bounds__(1024) k_scan3() {
    int i = blockIdx.x * 1024 + threadIdx.x;
    if (i < NN) {
        int rs = g_row_start[i] + g_poff[blockIdx.x];
        g_row_start[i] = rs;
        g_cursor[i]    = rs;
        g_invdeg[i]    = 1.0f / fmaxf((float)g_deg[i], 1.0f);
    }
}

__global__ void k_bucket(const int* __restrict__ src, const int* __restrict__ dst) {
    int e = blockIdx.x * blockDim.x + threadIdx.x;
    if (e < NE) {
        int d = dst[e];
        int p = atomicAdd(&g_cursor[d], 1);
        g_csr[p] = src[e];
    }
}

// ======= mean aggregation (fused bias + relu): out = relu(y + agg(y)/deg + b)
// 16 threads per node, float4 per thread, 8-neighbor unroll.
__global__ void __launch_bounds__(256) k_aggr(const float* __restrict__ y,
                                              const float* __restrict__ bias,
                                              float* __restrict__ out) {
    int node = blockIdx.x * 16 + (threadIdx.x >> 4);
    int c4 = (threadIdx.x & 15) * 4;
    int beg = g_row_start[node], end = g_row_start[node + 1];
    float4 acc = make_float4(0.f, 0.f, 0.f, 0.f);
    int e = beg;
    for (; e + 7 < end; e += 8) {
        int sI[8];
        #pragma unroll
        for (int u = 0; u < 8; u++) sI[u] = __ldg(&g_csr[e + u]);
        float4 v[8];
        #pragma unroll
        for (int u = 0; u < 8; u++)
            v[u] = *reinterpret_cast<const float4*>(y + (size_t)sI[u] * 64 + c4);
        #pragma unroll
        for (int u = 0; u < 8; u++) {
            acc.x += v[u].x; acc.y += v[u].y;
            acc.z += v[u].z; acc.w += v[u].w;
        }
    }
    for (; e < end; e++) {
        int s = __ldg(&g_csr[e]);
        float4 v = *reinterpret_cast<const float4*>(y + (size_t)s * 64 + c4);
        acc.x += v.x; acc.y += v.y; acc.z += v.z; acc.w += v.w;
    }
    float inv = g_invdeg[node];
    float4 self = *reinterpret_cast<const float4*>(y + (size_t)node * 64 + c4);
    float4 b = *reinterpret_cast<const float4*>(bias + c4);
    float4 r;
    r.x = fmaxf(self.x + acc.x * inv + b.x, 0.0f);
    r.y = fmaxf(self.y + acc.y * inv + b.y, 0.0f);
    r.z = fmaxf(self.z + acc.z * inv + b.z, 0.0f);
    r.w = fmaxf(self.w + acc.w * inv + b.w, 0.0f);
    *reinterpret_cast<float4*>(out + (size_t)node * 64 + c4) = r;
}

// ============ dense GEMM with packed f32x2: out = Z @ W + bias ============
// Z staged row-pair-interleaved in smem so LDS.128 yields packed f32x2 pairs.
#define FMA2(c, a, b) asm("fma.rn.f32x2 %0, %1, %2, %3;" \
                          : "=l"(c) : "l"(a), "l"(b), "l"(c))
__device__ __forceinline__ unsigned long long pk(float lo, float hi) {
    unsigned long long r = (unsigned long long)__float_as_uint(lo);
    return r | ((unsigned long long)__float_as_uint(hi) << 32);
}

#define GRT 40
#define GNT 320
template <int K>
__global__ void __launch_bounds__(GNT) k_gemm(const float* __restrict__ Z,
                                              const float* __restrict__ W,
                                              const float* __restrict__ bias,
                                              float* __restrict__ out) {
    constexpr int KP = K + 4;
    constexpr int PSTR = 2 * K + 8;    // floats per row-pair (16B-aligned)
    extern __shared__ float smg[];
    float* Ws  = smg;                  // [64 * KP]
    float* Zs2 = smg + 64 * KP;        // [20 * PSTR] row-pair interleaved
    int tid = threadIdx.x;
    int j = tid % 64, rg = tid / 64;   // rg in 0..4
    for (int idx = tid; idx < K * 64; idx += GNT) {
        int k = idx >> 6, c = idx & 63;
        Ws[c * KP + k] = W[idx];
    }
    int row0 = blockIdx.x * GRT;
    for (int idx = tid; idx < GRT * (K / 4); idx += GNT) {
        int r = idx / (K / 4), kq = idx % (K / 4);
        float4 v = reinterpret_cast<const float4*>(Z + (size_t)(row0 + r) * K)[kq];
        float* zb = Zs2 + (r >> 1) * PSTR + (r & 1) + 8 * kq;
        zb[0] = v.x; zb[2] = v.y; zb[4] = v.z; zb[6] = v.w;
    }
    __syncthreads();
    float bj = bias[j];
    unsigned long long acc2[4];
    #pragma unroll
    for (int rp = 0; rp < 4; rp++) acc2[rp] = pk(bj, bj);
    const float4* w4 = reinterpret_cast<const float4*>(&Ws[j * KP]);
    #pragma unroll 8
    for (int k4 = 0; k4 < K / 4; k4++) {
        float4 w = w4[k4];
        unsigned long long w0 = pk(w.x, w.x), w1 = pk(w.y, w.y);
        unsigned long long w2 = pk(w.z, w.z), w3 = pk(w.w, w.w);
        #pragma unroll
        for (int rp = 0; rp < 4; rp++) {
            const ulonglong2* zp = reinterpret_cast<const ulonglong2*>(
                &Zs2[(rg * 4 + rp) * PSTR + 8 * k4]);
            ulonglong2 A = zp[0], B = zp[1];
            FMA2(acc2[rp], A.x, w0);
            FMA2(acc2[rp], A.y, w1);
            FMA2(acc2[rp], B.x, w2);
            FMA2(acc2[rp], B.y, w3);
        }
    }
    #pragma unroll
    for (int rp = 0; rp < 4; rp++) {
        float lo = __uint_as_float((unsigned)acc2[rp]);
        float hi = __uint_as_float((unsigned)(acc2[rp] >> 32));
        out[(size_t)(row0 + rg * 8 + 2 * rp) * 64 + j]     = lo;
        out[(size_t)(row0 + rg * 8 + 2 * rp + 1) * 64 + j] = hi;
    }
}

// ======================= fused edge MLP on mma.sync (HMMA.16816) =======================
// Per 128-edge tile: A'[128 x 256] = [hs|hd|p|q] in fp16 (single precision pass).
// B = fp16(We1) [256 x 64] held in REGISTERS (per-warp fragments), loaded once.
#define ET 128
#define ETILES (NE / ET)         // 6250
#define ROWB 528                 // 264 halfs per A row (8-half pad)
#define OFF_AH 1024
#define SMEM_EDGE (OFF_AH + 128 * ROWB)   // 68608 bytes

__device__ __forceinline__ uint32_t smem_u32(const void* p) {
    uint32_t a;
    asm("{ .reg .u64 t; cvta.to.shared.u64 t, %1; cvt.u32.u64 %0, t; }"
        : "=r"(a) : "l"(p));
    return a;
}

#define LDSM4(r, addr)                                                         \
    asm volatile("ldmatrix.sync.aligned.m8n8.x4.shared.b16 {%0,%1,%2,%3}, [%4];" \
                 : "=r"((r)[0]), "=r"((r)[1]), "=r"((r)[2]), "=r"((r)[3])      \
                 : "r"(addr))

#define MMA16816(d, a, b)                                                      \
    asm volatile("mma.sync.aligned.m16n8k16.row.col.f32.f16.f16.f32 "          \
                 "{%0,%1,%2,%3},{%4,%5,%6,%7},{%8,%9},{%0,%1,%2,%3};"          \
                 : "+f"((d)[0]), "+f"((d)[1]), "+f"((d)[2]), "+f"((d)[3])      \
                 : "r"((a)[0]), "r"((a)[1]), "r"((a)[2]), "r"((a)[3]),         \
                   "r"((b)[0]), "r"((b)[1]))

__device__ __forceinline__ void write8h(char* ah, int koff2, const float* v) {
    uint32_t hi[4];
    #pragma unroll
    for (int i = 0; i < 4; i++) {
        __half2 h = __floats2half2_rn(v[2 * i], v[2 * i + 1]);
        hi[i] = *reinterpret_cast<uint32_t*>(&h);
    }
    *reinterpret_cast<uint4*>(ah + koff2) = make_uint4(hi[0], hi[1], hi[2], hi[3]);
}

__global__ void __launch_bounds__(256, 1) k_edge(
    const float* __restrict__ H, const int* __restrict__ src,
    const int* __restrict__ dst, const float* __restrict__ We1,
    const float* __restrict__ be1, const float* __restrict__ We2,
    const float* __restrict__ be2,
    float* __restrict__ logits, float* __restrict__ probs) {
    extern __shared__ char sm[];
    float* sred = reinterpret_cast<float*>(sm);       // 256 floats
    char* AhB = sm + OFF_AH;

    int tid = threadIdx.x, lane = tid & 31, wid = tid >> 5;
    int mw = wid & 3, nw = wid >> 2;

    // ---- load B fragments into registers (once per block) ----
    uint32_t bF[16][4][2];
    #pragma unroll
    for (int s = 0; s < 16; s++)
        #pragma unroll
        for (int j = 0; j < 4; j++)
            #pragma unroll
            for (int r = 0; r < 2; r++) {
                int k = s * 16 + 2 * (lane & 3) + r * 8;
                int n = nw * 32 + j * 8 + (lane >> 2);
                __half2 h = __floats2half2_rn(__ldg(&We1[k * 64 + n]),
                                              __ldg(&We1[(k + 1) * 64 + n]));
                bF[s][j][r] = *reinterpret_cast<uint32_t*>(&h);
            }
    float bb[4][2], ww[4][2];
    #pragma unroll
    for (int j = 0; j < 4; j++)
        #pragma unroll
        for (int c = 0; c < 2; c++) {
            int nc = nw * 32 + j * 8 + 2 * (lane & 3) + c;
            bb[j][c] = __ldg(&be1[nc]);
            ww[j][c] = __ldg(&We2[nc]);
        }
    float be2v = be2[0];

    int el = tid >> 1, q = tid & 1;        // staging: 2 threads / edge
    uint32_t AhAddr = smem_u32(AhB);
    uint32_t mrow = (uint32_t)(mw * 32 + (lane & 15)) * ROWB + (lane >> 4) * 16;

    for (int tile = blockIdx.x; tile < ETILES; tile += gridDim.x) {
        int e0 = tile * ET;
        // ---- stage A' (fp16) ----
        {
            int s = src[e0 + el], d = dst[e0 + el];
            const float4* hsP =
                reinterpret_cast<const float4*>(H + (size_t)s * 64 + q * 32);
            const float4* hdP =
                reinterpret_cast<const float4*>(H + (size_t)d * 64 + q * 32);
            char* rAh = AhB + el * ROWB;
            #pragma unroll
            for (int c = 0; c < 4; c++) {
                float4 a0 = hsP[2 * c], a1 = hsP[2 * c + 1];
                float4 b0 = hdP[2 * c], b1 = hdP[2 * c + 1];
                float hs8[8] = {a0.x, a0.y, a0.z, a0.w, a1.x, a1.y, a1.z, a1.w};
                float hd8[8] = {b0.x, b0.y, b0.z, b0.w, b1.x, b1.y, b1.z, b1.w};
                float p8[8], q8[8];
                #pragma unroll
                for (int i = 0; i < 8; i++) {
                    p8[i] = hs8[i] * hd8[i];
                    q8[i] = fabsf(hs8[i] - hd8[i]);
                }
                int kb = (32 * q + 8 * c) * 2;
                write8h(rAh, kb, hs8);
                write8h(rAh, kb + 128, hd8);
                write8h(rAh, kb + 256, p8);
                write8h(rAh, kb + 384, q8);
            }
        }
        __syncthreads();

        // ---- MMA: K=256, single fp16 pass ----
        float dacc[2][4][4];
        #pragma unroll
        for (int t = 0; t < 2; t++)
            #pragma unroll
            for (int j = 0; j < 4; j++)
                #pragma unroll
                for (int r = 0; r < 4; r++) dacc[t][j][r] = 0.0f;

        uint32_t base = AhAddr + mrow;
        #pragma unroll
        for (int s = 0; s < 16; s++) {
            uint32_t a0[4], a1[4];
            LDSM4(a0, base + s * 32);
            LDSM4(a1, base + 16 * ROWB + s * 32);
            #pragma unroll
            for (int j = 0; j < 4; j++) {
                MMA16816(dacc[0][j], a0, bF[s][j]);
                MMA16816(dacc[1][j], a1, bF[s][j]);
            }
        }

        // ---- epilogue: relu(D+be1).We2, quad reduce, smem combine ----
        #pragma unroll
        for (int t = 0; t < 2; t++) {
            float p0 = 0.0f, p1 = 0.0f;
            #pragma unroll
            for (int j = 0; j < 4; j++) {
                p0 += fmaxf(dacc[t][j][0] + bb[j][0], 0.0f) * ww[j][0];
                p0 += fmaxf(dacc[t][j][1] + bb[j][1], 0.0f) * ww[j][1];
                p1 += fmaxf(dacc[t][j][2] + bb[j][0], 0.0f) * ww[j][0];
                p1 += fmaxf(dacc[t][j][3] + bb[j][1], 0.0f) * ww[j][1];
            }
            p0 += __shfl_xor_sync(0xffffffffu, p0, 1);
            p0 += __shfl_xor_sync(0xffffffffu, p0, 2);
            p1 += __shfl_xor_sync(0xffffffffu, p1, 1);
            p1 += __shfl_xor_sync(0xffffffffu, p1, 2);
            if ((lane & 3) == 0) {
                int r = mw * 32 + 16 * t + (lane >> 2);
                sred[r + 128 * nw]     = p0;
                sred[r + 8 + 128 * nw] = p1;
            }
        }
        __syncthreads();
        if (tid < 128) {
            float l = sred[tid] + sred[tid + 128] + be2v;
            logits[e0 + tid] = l;
            probs[e0 + tid]  = 1.0f / (1.0f + expf(-l));
        }
        __syncthreads();
    }
}

// ======================= launcher =======================
extern "C" void kernel_launch(void* const* d_in, const int* in_sizes, int n_in,
                              void* d_out, int out_size) {
    const float* x   = (const float*)d_in[0];
    const float* W1  = (const float*)d_in[1];
    const float* b1  = (const float*)d_in[2];
    const float* W2  = (const float*)d_in[3];
    const float* b2  = (const float*)d_in[4];
    const float* We1 = (const float*)d_in[5];
    const float* be1 = (const float*)d_in[6];
    const float* We2 = (const float*)d_in[7];
    const float* be2 = (const float*)d_in[8];
    const int*   ei  = (const int*)d_in[9];
    const int* src = ei;
    const int* dst = ei + NE;

    float* out    = (float*)d_out;
    float* H      = out;                 // [NN, 64]
    float* logits = out + NN * HID;      // [NE]
    float* probs  = logits + NE;         // [NE]

    void *yp, *h1p, *y2p, *zp;
    cudaGetSymbolAddress(&yp, g_y);
    cudaGetSymbolAddress(&h1p, g_h1);
    cudaGetSymbolAddress(&y2p, g_y2);
    cudaGetSymbolAddress(&zp, g_zeros);

    // CSR build (parallel scan)
    k_zero<<<(NN + 255) / 256, 256>>>();
    k_count<<<(NE + 255) / 256, 256>>>(dst);
    k_scan1<<<NSCH, 1024>>>();
    k_scan2<<<1, 64>>>();
    k_scan3<<<NSCH, 1024>>>();
    k_bucket<<<(NE + 255) / 256, 256>>>(src, dst);

    // dynamic smem sizes for the gemms
    int sm128 = (64 * (INDIM + 4) + 20 * (2 * INDIM + 8)) * (int)sizeof(float);
    int sm64  = (64 * (HID + 4)   + 20 * (2 * HID + 8))   * (int)sizeof(float);
    cudaFuncSetAttribute(k_gemm<INDIM>,
                         cudaFuncAttributeMaxDynamicSharedMemorySize, sm128);
    cudaFuncSetAttribute(k_gemm<HID>,
                         cudaFuncAttributeMaxDynamicSharedMemorySize, sm64);

    // encoder layer 1 (GEMM first, then 64-dim aggregation; linearity commute)
    k_gemm<INDIM><<<NN / GRT, GNT, sm128>>>(x, W1, (const float*)zp, (float*)yp);
    k_aggr<<<NN / 16, 256>>>((const float*)yp, b1, (float*)h1p);
    // encoder layer 2 -> H into d_out
    k_gemm<HID><<<NN / GRT, GNT, sm64>>>((const float*)h1p, W2, (const float*)zp,
                                         (float*)y2p);
    k_aggr<<<NN / 16, 256>>>((const float*)y2p, b2, H);

    // fused edge MLP on tensor cores (mma.sync, single fp16 pass)
    cudaFuncSetAttribute(k_edge, cudaFuncAttributeMaxDynamicSharedMemorySize,
                         SMEM_EDGE);
    k_edge<<<148, 256, SMEM_EDGE>>>(H, src, dst, We1, be1, We2, be2,
                                    logits, probs);
}

// round 9
// speedup vs baseline: 3.8943x; 1.0345x over previous
#include <cuda_runtime.h>
#include <cuda_fp16.h>
#include <cstdint>
#include <math.h>

#define NN 50000
#define NE 800000
#define INDIM 128
#define HID 64
#define NSCH 49   // ceil(NN/1024)

// ======================= device scratch =======================
__device__ int   g_deg[NN];
__device__ int   g_row_start[NN + 1];
__device__ int   g_cursor[NN];
__device__ int   g_csr[NE];
__device__ float g_invdeg[NN];
__device__ int   g_psum[64];
__device__ int   g_poff[64];
__device__ float g_y[NN * HID];
__device__ float g_h1[NN * HID];
__device__ float g_y2[NN * HID];
__device__ float g_zeros[128];

// ======================= CSR build =======================
__global__ void k_zero() {
    int i = blockIdx.x * blockDim.x + threadIdx.x;
    if (i < NN) g_deg[i] = 0;
}

__global__ void k_count(const int* __restrict__ dst) {
    int e = blockIdx.x * blockDim.x + threadIdx.x;
    if (e < NE) atomicAdd(&g_deg[dst[e]], 1);
}

__global__ void __launch_bounds__(1024) k_scan1() {
    __shared__ int wsum[32];
    int tid = threadIdx.x;
    int i = blockIdx.x * 1024 + tid;
    int v = (i < NN) ? g_deg[i] : 0;
    int xv = v;
    #pragma unroll
    for (int o = 1; o < 32; o <<= 1) {
        int y = __shfl_up_sync(0xffffffffu, xv, o);
        if ((tid & 31) >= o) xv += y;
    }
    if ((tid & 31) == 31) wsum[tid >> 5] = xv;
    __syncthreads();
    if (tid < 32) {
        int s = wsum[tid];
        #pragma unroll
        for (int o = 1; o < 32; o <<= 1) {
            int y = __shfl_up_sync(0xffffffffu, s, o);
            if (tid >= o) s += y;
        }
        wsum[tid] = s;
    }
    __syncthreads();
    int add = (tid >= 32) ? wsum[(tid >> 5) - 1] : 0;
    if (i < NN) g_row_start[i] = xv + add - v;
    if (tid == 0) g_psum[blockIdx.x] = wsum[31];
}

__global__ void k_scan2() {
    __shared__ int ws;
    int tid = threadIdx.x;   // 64
    int v = (tid < NSCH) ? g_psum[tid] : 0;
    int x = v;
    #pragma unroll
    for (int o = 1; o < 32; o <<= 1) {
        int y = __shfl_up_sync(0xffffffffu, x, o);
        if ((tid & 31) >= o) x += y;
    }
    if (tid == 31) ws = x;
    __syncthreads();
    int incl = x + ((tid >= 32) ? ws : 0);
    if (tid < NSCH) g_poff[tid] = incl - v;
    if (tid == NSCH - 1) g_row_start[NN] = incl;
}

__global__ void __launch_bounds__(1024) k_scan3() {
    int i = blockIdx.x * 1024 + threadIdx.x;
    if (i < NN) {
        int rs = g_row_start[i] + g_poff[blockIdx.x];
        g_row_start[i] = rs;
        g_cursor[i]    = rs;
        g_invdeg[i]    = 1.0f / fmaxf((float)g_deg[i], 1.0f);
    }
}

__global__ void k_bucket(const int* __restrict__ src, const int* __restrict__ dst) {
    int e = blockIdx.x * blockDim.x + threadIdx.x;
    if (e < NE) {
        int d = dst[e];
        int p = atomicAdd(&g_cursor[d], 1);
        g_csr[p] = src[e];
    }
}

// ======= mean aggregation (fused bias + relu): out = relu(y + agg(y)/deg + b)
__global__ void __launch_bounds__(256) k_aggr(const float* __restrict__ y,
                                              const float* __restrict__ bias,
                                              float* __restrict__ out) {
    int node = blockIdx.x * 16 + (threadIdx.x >> 4);
    int c4 = (threadIdx.x & 15) * 4;
    int beg = g_row_start[node], end = g_row_start[node + 1];
    float4 acc = make_float4(0.f, 0.f, 0.f, 0.f);
    int e = beg;
    for (; e + 7 < end; e += 8) {
        int sI[8];
        #pragma unroll
        for (int u = 0; u < 8; u++) sI[u] = __ldg(&g_csr[e + u]);
        float4 v[8];
        #pragma unroll
        for (int u = 0; u < 8; u++)
            v[u] = *reinterpret_cast<const float4*>(y + (size_t)sI[u] * 64 + c4);
        #pragma unroll
        for (int u = 0; u < 8; u++) {
            acc.x += v[u].x; acc.y += v[u].y;
            acc.z += v[u].z; acc.w += v[u].w;
        }
    }
    for (; e < end; e++) {
        int s = __ldg(&g_csr[e]);
        float4 v = *reinterpret_cast<const float4*>(y + (size_t)s * 64 + c4);
        acc.x += v.x; acc.y += v.y; acc.z += v.z; acc.w += v.w;
    }
    float inv = g_invdeg[node];
    float4 self = *reinterpret_cast<const float4*>(y + (size_t)node * 64 + c4);
    float4 b = *reinterpret_cast<const float4*>(bias + c4);
    float4 r;
    r.x = fmaxf(self.x + acc.x * inv + b.x, 0.0f);
    r.y = fmaxf(self.y + acc.y * inv + b.y, 0.0f);
    r.z = fmaxf(self.z + acc.z * inv + b.z, 0.0f);
    r.w = fmaxf(self.w + acc.w * inv + b.w, 0.0f);
    *reinterpret_cast<float4*>(out + (size_t)node * 64 + c4) = r;
}

// ============ dense GEMM with packed f32x2: out = Z @ W + bias ============
#define FMA2(c, a, b) asm("fma.rn.f32x2 %0, %1, %2, %3;" \
                          : "=l"(c) : "l"(a), "l"(b), "l"(c))
__device__ __forceinline__ unsigned long long pk(float lo, float hi) {
    unsigned long long r = (unsigned long long)__float_as_uint(lo);
    return r | ((unsigned long long)__float_as_uint(hi) << 32);
}

#define GRT 40
#define GNT 320
template <int K>
__global__ void __launch_bounds__(GNT) k_gemm(const float* __restrict__ Z,
                                              const float* __restrict__ W,
                                              const float* __restrict__ bias,
                                              float* __restrict__ out) {
    constexpr int KP = K + 4;
    constexpr int PSTR = 2 * K + 8;
    extern __shared__ float smg[];
    float* Ws  = smg;
    float* Zs2 = smg + 64 * KP;
    int tid = threadIdx.x;
    int j = tid % 64, rg = tid / 64;
    for (int idx = tid; idx < K * 64; idx += GNT) {
        int k = idx >> 6, c = idx & 63;
        Ws[c * KP + k] = W[idx];
    }
    int row0 = blockIdx.x * GRT;
    for (int idx = tid; idx < GRT * (K / 4); idx += GNT) {
        int r = idx / (K / 4), kq = idx % (K / 4);
        float4 v = reinterpret_cast<const float4*>(Z + (size_t)(row0 + r) * K)[kq];
        float* zb = Zs2 + (r >> 1) * PSTR + (r & 1) + 8 * kq;
        zb[0] = v.x; zb[2] = v.y; zb[4] = v.z; zb[6] = v.w;
    }
    __syncthreads();
    float bj = bias[j];
    unsigned long long acc2[4];
    #pragma unroll
    for (int rp = 0; rp < 4; rp++) acc2[rp] = pk(bj, bj);
    const float4* w4 = reinterpret_cast<const float4*>(&Ws[j * KP]);
    #pragma unroll 8
    for (int k4 = 0; k4 < K / 4; k4++) {
        float4 w = w4[k4];
        unsigned long long w0 = pk(w.x, w.x), w1 = pk(w.y, w.y);
        unsigned long long w2 = pk(w.z, w.z), w3 = pk(w.w, w.w);
        #pragma unroll
        for (int rp = 0; rp < 4; rp++) {
            const ulonglong2* zp = reinterpret_cast<const ulonglong2*>(
                &Zs2[(rg * 4 + rp) * PSTR + 8 * k4]);
            ulonglong2 A = zp[0], B = zp[1];
            FMA2(acc2[rp], A.x, w0);
            FMA2(acc2[rp], A.y, w1);
            FMA2(acc2[rp], B.x, w2);
            FMA2(acc2[rp], B.y, w3);
        }
    }
    #pragma unroll
    for (int rp = 0; rp < 4; rp++) {
        float lo = __uint_as_float((unsigned)acc2[rp]);
        float hi = __uint_as_float((unsigned)(acc2[rp] >> 32));
        out[(size_t)(row0 + rg * 8 + 2 * rp) * 64 + j]     = lo;
        out[(size_t)(row0 + rg * 8 + 2 * rp + 1) * 64 + j] = hi;
    }
}

// ======================= fused edge MLP: cp.async pipelined mma.sync =======================
// Pipeline: cp.async prefetches next tile's raw fp32 H rows into smem during the
// current tile's MMA+epilogue; convert (fp32->fp16 [hs|hd|p|q]) reads smem only.
#define ET 128
#define ETILES (NE / ET)         // 6250
#define ROWB 528                 // A row: 264 halfs (8-half pad)
#define RAWB 544                 // raw: hs 256B @0, hd 256B @272 (pad for banks)
#define OFF_AH 1024
#define OFF_RAW (OFF_AH + 128 * ROWB)        // 68608
#define SMEM_EDGE (OFF_RAW + 128 * RAWB)     // 138240

__device__ __forceinline__ uint32_t smem_u32(const void* p) {
    uint32_t a;
    asm("{ .reg .u64 t; cvta.to.shared.u64 t, %1; cvt.u32.u64 %0, t; }"
        : "=r"(a) : "l"(p));
    return a;
}

#define CP16(d, s) asm volatile("cp.async.cg.shared.global [%0], [%1], 16;" \
                                :: "r"(d), "l"(s))
#define CP_COMMIT() asm volatile("cp.async.commit_group;" ::: "memory")
#define CP_WAIT0()  asm volatile("cp.async.wait_group 0;" ::: "memory")

#define LDSM4(r, addr)                                                         \
    asm volatile("ldmatrix.sync.aligned.m8n8.x4.shared.b16 {%0,%1,%2,%3}, [%4];" \
                 : "=r"((r)[0]), "=r"((r)[1]), "=r"((r)[2]), "=r"((r)[3])      \
                 : "r"(addr))

#define MMA16816(d, a, b)                                                      \
    asm volatile("mma.sync.aligned.m16n8k16.row.col.f32.f16.f16.f32 "          \
                 "{%0,%1,%2,%3},{%4,%5,%6,%7},{%8,%9},{%0,%1,%2,%3};"          \
                 : "+f"((d)[0]), "+f"((d)[1]), "+f"((d)[2]), "+f"((d)[3])      \
                 : "r"((a)[0]), "r"((a)[1]), "r"((a)[2]), "r"((a)[3]),         \
                   "r"((b)[0]), "r"((b)[1]))

__device__ __forceinline__ void write8h(char* ah, int koff2, const float* v) {
    uint32_t hi[4];
    #pragma unroll
    for (int i = 0; i < 4; i++) {
        __half2 h = __floats2half2_rn(v[2 * i], v[2 * i + 1]);
        hi[i] = *reinterpret_cast<uint32_t*>(&h);
    }
    *reinterpret_cast<uint4*>(ah + koff2) = make_uint4(hi[0], hi[1], hi[2], hi[3]);
}

__global__ void __launch_bounds__(256, 1) k_edge(
    const float* __restrict__ H, const int* __restrict__ src,
    const int* __restrict__ dst, const float* __restrict__ We1,
    const float* __restrict__ be1, const float* __restrict__ We2,
    const float* __restrict__ be2,
    float* __restrict__ logits, float* __restrict__ probs) {
    extern __shared__ char sm[];
    float* sred = reinterpret_cast<float*>(sm);
    char* AhB  = sm + OFF_AH;
    char* rawB = sm + OFF_RAW;

    int tid = threadIdx.x, lane = tid & 31, wid = tid >> 5;
    int mw = wid & 3, nw = wid >> 2;

    // ---- load B fragments into registers (once per block) ----
    uint32_t bF[16][4][2];
    #pragma unroll
    for (int s = 0; s < 16; s++)
        #pragma unroll
        for (int j = 0; j < 4; j++)
            #pragma unroll
            for (int r = 0; r < 2; r++) {
                int k = s * 16 + 2 * (lane & 3) + r * 8;
                int n = nw * 32 + j * 8 + (lane >> 2);
                __half2 h = __floats2half2_rn(__ldg(&We1[k * 64 + n]),
                                              __ldg(&We1[(k + 1) * 64 + n]));
                bF[s][j][r] = *reinterpret_cast<uint32_t*>(&h);
            }
    float bb[4][2], ww[4][2];
    #pragma unroll
    for (int j = 0; j < 4; j++)
        #pragma unroll
        for (int c = 0; c < 2; c++) {
            int nc = nw * 32 + j * 8 + 2 * (lane & 3) + c;
            bb[j][c] = __ldg(&be1[nc]);
            ww[j][c] = __ldg(&We2[nc]);
        }
    float be2v = be2[0];

    int el = tid >> 1, q = tid & 1;    // this thread owns edge el, half q
    const int* idxp = q ? dst : src;   // q=0 copies hs row, q=1 copies hd row
    uint32_t rawDst = smem_u32(rawB + el * RAWB + q * 272);
    uint32_t AhAddr = smem_u32(AhB);
    uint32_t mrow = (uint32_t)(mw * 32 + (lane & 15)) * ROWB + (lane >> 4) * 16;
    int G = gridDim.x;

    // ---- prologue: prefetch raw rows for first tile; preload next indices ----
    int tile0 = blockIdx.x;
    {
        int n0 = __ldg(&idxp[tile0 * ET + el]);
        const char* s0 = (const char*)(H + (size_t)n0 * 64);
        #pragma unroll
        for (int k = 0; k < 16; k++) CP16(rawDst + k * 16, s0 + k * 16);
        CP_COMMIT();
    }
    int tnext = tile0 + G;
    int nnext = (tnext < ETILES) ? __ldg(&idxp[tnext * ET + el]) : 0;

    for (int tile = tile0; tile < ETILES; tile += G) {
        int e0 = tile * ET;
        CP_WAIT0();
        __syncthreads();   // raw[tile] visible to all threads

        // ---- convert: raw fp32 (smem) -> fp16 A' [hs|hd|p|q] ----
        {
            const float4* rhs = reinterpret_cast<const float4*>(
                rawB + el * RAWB + q * 128);
            const float4* rhd = reinterpret_cast<const float4*>(
                rawB + el * RAWB + 272 + q * 128);
            char* rAh = AhB + el * ROWB;
            #pragma unroll
            for (int c = 0; c < 4; c++) {
                float4 a0 = rhs[2 * c], a1 = rhs[2 * c + 1];
                float4 b0 = rhd[2 * c], b1 = rhd[2 * c + 1];
                float hs8[8] = {a0.x, a0.y, a0.z, a0.w, a1.x, a1.y, a1.z, a1.w};
                float hd8[8] = {b0.x, b0.y, b0.z, b0.w, b1.x, b1.y, b1.z, b1.w};
                float p8[8], q8[8];
                #pragma unroll
                for (int i = 0; i < 8; i++) {
                    p8[i] = hs8[i] * hd8[i];
                    q8[i] = fabsf(hs8[i] - hd8[i]);
                }
                int kb = (32 * q + 8 * c) * 2;
                write8h(rAh, kb, hs8);
                write8h(rAh, kb + 128, hd8);
                write8h(rAh, kb + 256, p8);
                write8h(rAh, kb + 384, q8);
            }
        }
        __syncthreads();   // A ready; raw consumed

        // ---- prefetch raw for next tile (overlaps MMA + epilogue) ----
        int tn = tile + G;
        if (tn < ETILES) {
            const char* sN = (const char*)(H + (size_t)nnext * 64);
            #pragma unroll
            for (int k = 0; k < 16; k++) CP16(rawDst + k * 16, sN + k * 16);
            CP_COMMIT();
            int tnn = tn + G;
            if (tnn < ETILES) nnext = __ldg(&idxp[tnn * ET + el]);
        }

        // ---- MMA: K=256, single fp16 pass ----
        float dacc[2][4][4];
        #pragma unroll
        for (int t = 0; t < 2; t++)
            #pragma unroll
            for (int j = 0; j < 4; j++)
                #pragma unroll
                for (int r = 0; r < 4; r++) dacc[t][j][r] = 0.0f;

        uint32_t base = AhAddr + mrow;
        #pragma unroll
        for (int s = 0; s < 16; s++) {
            uint32_t a0[4], a1[4];
            LDSM4(a0, base + s * 32);
            LDSM4(a1, base + 16 * ROWB + s * 32);
            #pragma unroll
            for (int j = 0; j < 4; j++) {
                MMA16816(dacc[0][j], a0, bF[s][j]);
                MMA16816(dacc[1][j], a1, bF[s][j]);
            }
        }

        // ---- epilogue: relu(D+be1).We2, quad reduce, smem combine ----
        #pragma unroll
        for (int t = 0; t < 2; t++) {
            float p0 = 0.0f, p1 = 0.0f;
            #pragma unroll
            for (int j = 0; j < 4; j++) {
                p0 += fmaxf(dacc[t][j][0] + bb[j][0], 0.0f) * ww[j][0];
                p0 += fmaxf(dacc[t][j][1] + bb[j][1], 0.0f) * ww[j][1];
                p1 += fmaxf(dacc[t][j][2] + bb[j][0], 0.0f) * ww[j][0];
                p1 += fmaxf(dacc[t][j][3] + bb[j][1], 0.0f) * ww[j][1];
            }
            p0 += __shfl_xor_sync(0xffffffffu, p0, 1);
            p0 += __shfl_xor_sync(0xffffffffu, p0, 2);
            p1 += __shfl_xor_sync(0xffffffffu, p1, 1);
            p1 += __shfl_xor_sync(0xffffffffu, p1, 2);
            if ((lane & 3) == 0) {
                int r = mw * 32 + 16 * t + (lane >> 2);
                sred[r + 128 * nw]     = p0;
                sred[r + 8 + 128 * nw] = p1;
            }
        }
        __syncthreads();
        if (tid < 128) {
            float l = sred[tid] + sred[tid + 128] + be2v;
            logits[e0 + tid] = l;
            probs[e0 + tid]  = 1.0f / (1.0f + expf(-l));
        }
        // no trailing barrier: next tile's convert-phase syncs order sred reuse
    }
}

// ======================= launcher =======================
extern "C" void kernel_launch(void* const* d_in, const int* in_sizes, int n_in,
                              void* d_out, int out_size) {
    const float* x   = (const float*)d_in[0];
    const float* W1  = (const float*)d_in[1];
    const float* b1  = (const float*)d_in[2];
    const float* W2  = (const float*)d_in[3];
    const float* b2  = (const float*)d_in[4];
    const float* We1 = (const float*)d_in[5];
    const float* be1 = (const float*)d_in[6];
    const float* We2 = (const float*)d_in[7];
    const float* be2 = (const float*)d_in[8];
    const int*   ei  = (const int*)d_in[9];
    const int* src = ei;
    const int* dst = ei + NE;

    float* out    = (float*)d_out;
    float* H      = out;                 // [NN, 64]
    float* logits = out + NN * HID;      // [NE]
    float* probs  = logits + NE;         // [NE]

    void *yp, *h1p, *y2p, *zp;
    cudaGetSymbolAddress(&yp, g_y);
    cudaGetSymbolAddress(&h1p, g_h1);
    cudaGetSymbolAddress(&y2p, g_y2);
    cudaGetSymbolAddress(&zp, g_zeros);

    // CSR build (parallel scan)
    k_zero<<<(NN + 255) / 256, 256>>>();
    k_count<<<(NE + 255) / 256, 256>>>(dst);
    k_scan1<<<NSCH, 1024>>>();
    k_scan2<<<1, 64>>>();
    k_scan3<<<NSCH, 1024>>>();
    k_bucket<<<(NE + 255) / 256, 256>>>(src, dst);

    int sm128 = (64 * (INDIM + 4) + 20 * (2 * INDIM + 8)) * (int)sizeof(float);
    int sm64  = (64 * (HID + 4)   + 20 * (2 * HID + 8))   * (int)sizeof(float);
    cudaFuncSetAttribute(k_gemm<INDIM>,
                         cudaFuncAttributeMaxDynamicSharedMemorySize, sm128);
    cudaFuncSetAttribute(k_gemm<HID>,
                         cudaFuncAttributeMaxDynamicSharedMemorySize, sm64);

    // encoder layer 1 (GEMM first, then 64-dim aggregation; linearity commute)
    k_gemm<INDIM><<<NN / GRT, GNT, sm128>>>(x, W1, (const float*)zp, (float*)yp);
    k_aggr<<<NN / 16, 256>>>((const float*)yp, b1, (float*)h1p);
    // encoder layer 2 -> H into d_out
    k_gemm<HID><<<NN / GRT, GNT, sm64>>>((const float*)h1p, W2, (const float*)zp,
                                         (float*)y2p);
    k_aggr<<<NN / 16, 256>>>((const float*)y2p, b2, H);

    // fused edge MLP (cp.async pipelined mma.sync)
    cudaFuncSetAttribute(k_edge, cudaFuncAttributeMaxDynamicSharedMemorySize,
                         SMEM_EDGE);
    k_edge<<<148, 256, SMEM_EDGE>>>(H, src, dst, We1, be1, We2, be2,
                                    logits, probs);
}